// round 6
// baseline (speedup 1.0000x reference)
#include <cuda_runtime.h>
#include <cuda_bf16.h>
#include <math.h>
#include <stdint.h>

#define NTOK 4096
#define EMB  1024
#define HID  4096
#define VOCAB 32000
#define SEQ  2048
#define NH   16
#define HD   64
#define NL   8

typedef __nv_bfloat16 bf16;
typedef __nv_bfloat162 bf162;

// ---------------- device scratch --------------------------------------------
__device__ __align__(16) float g_x[NTOK * EMB];
__device__ __align__(16) float g_qkv[NTOK * 3 * EMB];

__device__ __align__(16) bf16 g_h_h[NTOK * EMB];
__device__ __align__(16) bf16 g_h_l[NTOK * EMB];
__device__ __align__(16) bf16 g_o_h[NTOK * EMB];
__device__ __align__(16) bf16 g_o_l[NTOK * EMB];
__device__ __align__(16) bf16 g_u_h[NTOK * HID];
__device__ __align__(16) bf16 g_u_l[NTOK * HID];

// transposed weights [N][K] hi/lo; QKV fused to [3E][E] per layer
__device__ __align__(16) bf16 g_Wqkv_h[NL * 3 * EMB * EMB];
__device__ __align__(16) bf16 g_Wqkv_l[NL * 3 * EMB * EMB];
__device__ __align__(16) bf16 g_Wp_h[NL * EMB * EMB];
__device__ __align__(16) bf16 g_Wp_l[NL * EMB * EMB];
__device__ __align__(16) bf16 g_W1_h[NL * EMB * HID];
__device__ __align__(16) bf16 g_W1_l[NL * EMB * HID];
__device__ __align__(16) bf16 g_W2_h[NL * EMB * HID];
__device__ __align__(16) bf16 g_W2_l[NL * EMB * HID];
__device__ __align__(16) bf16 g_Wo_h[(size_t)VOCAB * EMB];
__device__ __align__(16) bf16 g_Wo_l[(size_t)VOCAB * EMB];

// ---------------- helpers ---------------------------------------------------
__device__ __forceinline__ uint32_t smem_u32(const void* p) {
    return (uint32_t)__cvta_generic_to_shared((void*)p);
}
__device__ __forceinline__ uint32_t pack_bf2(float a, float b) {
    bf162 t = __floats2bfloat162_rn(a, b);
    return *reinterpret_cast<uint32_t*>(&t);
}
__device__ __forceinline__ void cpa16(uint32_t dst, const void* src) {
    asm volatile("cp.async.ca.shared.global [%0], [%1], 16;" :: "r"(dst), "l"(src));
}
#define CPA_COMMIT() asm volatile("cp.async.commit_group;" ::: "memory")
#define CPA_WAIT2()  asm volatile("cp.async.wait_group 2;" ::: "memory")

#define LDSM4(r, a) \
    asm volatile("ldmatrix.sync.aligned.m8n8.x4.shared.b16 {%0,%1,%2,%3}, [%4];" \
        : "=r"((r)[0]), "=r"((r)[1]), "=r"((r)[2]), "=r"((r)[3]) : "r"(a))

#define MMA16816(d, a, b) \
    asm volatile("mma.sync.aligned.m16n8k16.row.col.f32.bf16.bf16.f32 " \
        "{%0,%1,%2,%3},{%4,%5,%6,%7},{%8,%9},{%0,%1,%2,%3};" \
        : "+f"((d)[0]), "+f"((d)[1]), "+f"((d)[2]), "+f"((d)[3]) \
        : "r"((a)[0]), "r"((a)[1]), "r"((a)[2]), "r"((a)[3]), \
          "r"((b)[0]), "r"((b)[1]))

// ---------------- all-weights transpose + split-convert ----------------------
// in: [K][N] fp32, out: [N][K] hi/lo bf16 (with optional row offset for QKV fuse)
__global__ void tconv_all(const float* __restrict__ Wq, const float* __restrict__ Wk,
                          const float* __restrict__ Wv, const float* __restrict__ Wp,
                          const float* __restrict__ W1, const float* __restrict__ W2,
                          const float* __restrict__ Wout,
                          bf16* __restrict__ qkvh, bf16* __restrict__ qkvl,
                          bf16* __restrict__ wph, bf16* __restrict__ wpl,
                          bf16* __restrict__ w1h, bf16* __restrict__ w1l,
                          bf16* __restrict__ w2h, bf16* __restrict__ w2l,
                          bf16* __restrict__ woh, bf16* __restrict__ wol) {
    __shared__ float t[32][33];
    int b = blockIdx.x;
    const float* src; bf16 *oh, *ol;
    int K, N, tilesX, tloc, rowOff = 0;

    if (b < 24576) {                       // Q,K,V -> fused [3E][E]
        int type = b / 8192, lb = b % 8192;
        int layer = lb / 1024; tloc = lb % 1024;
        K = 1024; N = 1024; tilesX = 32;
        src = (type == 0 ? Wq : type == 1 ? Wk : Wv) + (size_t)layer * EMB * EMB;
        oh = qkvh + (size_t)layer * 3 * EMB * EMB;
        ol = qkvl + (size_t)layer * 3 * EMB * EMB;
        rowOff = type * 1024;
    } else if (b < 32768) {                // Wp
        int lb = b - 24576;
        int layer = lb / 1024; tloc = lb % 1024;
        K = 1024; N = 1024; tilesX = 32;
        src = Wp + (size_t)layer * EMB * EMB;
        oh = wph + (size_t)layer * EMB * EMB;
        ol = wpl + (size_t)layer * EMB * EMB;
    } else if (b < 65536) {                // W1 [1024][4096]
        int lb = b - 32768;
        int layer = lb / 4096; tloc = lb % 4096;
        K = 1024; N = 4096; tilesX = 128;
        src = W1 + (size_t)layer * EMB * HID;
        oh = w1h + (size_t)layer * EMB * HID;
        ol = w1l + (size_t)layer * EMB * HID;
    } else if (b < 98304) {                // W2 [4096][1024]
        int lb = b - 65536;
        int layer = lb / 4096; tloc = lb % 4096;
        K = 4096; N = 1024; tilesX = 32;
        src = W2 + (size_t)layer * HID * EMB;
        oh = w2h + (size_t)layer * HID * EMB;
        ol = w2l + (size_t)layer * HID * EMB;
    } else {                               // Wout [1024][32000]
        tloc = b - 98304;
        K = 1024; N = VOCAB; tilesX = 1000;
        src = Wout; oh = woh; ol = wol;
    }

    int bx = (tloc % tilesX) * 32;
    int by = (tloc / tilesX) * 32;
    int x = threadIdx.x, y = threadIdx.y;
    #pragma unroll
    for (int i = 0; i < 4; i++)
        t[y + i * 8][x] = src[(size_t)(by + y + i * 8) * N + bx + x];
    __syncthreads();
    #pragma unroll
    for (int i = 0; i < 4; i++) {
        int n = bx + y + i * 8, k = by + x;
        float v = t[x][y + i * 8];
        bf16 hv = __float2bfloat16(v);
        oh[(size_t)(rowOff + n) * K + k] = hv;
        ol[(size_t)(rowOff + n) * K + k] = __float2bfloat16(v - __bfloat162float(hv));
    }
}

// ---------------- embed ------------------------------------------------------
__global__ void embed_kernel(const int* __restrict__ idx, const float* __restrict__ tok,
                             const float* __restrict__ pos, float* __restrict__ x) {
    int n = blockIdx.x, e4 = threadIdx.x, t = n & (SEQ - 1);
    float4 a = ((const float4*)(tok + (size_t)idx[n] * EMB))[e4];
    float4 b = ((const float4*)(pos + (size_t)t * EMB))[e4];
    a.x += b.x; a.y += b.y; a.z += b.z; a.w += b.w;
    ((float4*)(x + (size_t)n * EMB))[e4] = a;
}

// ---------------- layernorm -> hi/lo bf16 ------------------------------------
__device__ __forceinline__ float block_sum_256(float s, float* red) {
    #pragma unroll
    for (int o = 16; o; o >>= 1) s += __shfl_xor_sync(0xffffffffu, s, o);
    if ((threadIdx.x & 31) == 0) red[threadIdx.x >> 5] = s;
    __syncthreads();
    if (threadIdx.x < 32) {
        float t = (threadIdx.x < 8) ? red[threadIdx.x] : 0.0f;
        #pragma unroll
        for (int o = 4; o; o >>= 1) t += __shfl_xor_sync(0xffffffffu, t, o);
        if (threadIdx.x == 0) red[0] = t;
    }
    __syncthreads();
    float r = red[0];
    __syncthreads();
    return r;
}

__global__ void ln_kernel(const float* __restrict__ x, const float* __restrict__ g,
                          const float* __restrict__ b, bf16* __restrict__ oh,
                          bf16* __restrict__ ol) {
    __shared__ float red[8];
    int n = blockIdx.x, tid = threadIdx.x;
    float4 v = ((const float4*)(x + (size_t)n * EMB))[tid];
    float mu = block_sum_256(v.x + v.y + v.z + v.w, red) * (1.0f / EMB);
    float dx = v.x - mu, dy = v.y - mu, dz = v.z - mu, dw = v.w - mu;
    float var = block_sum_256(dx*dx + dy*dy + dz*dz + dw*dw, red) * (1.0f / EMB);
    float rs = rsqrtf(var + 1e-5f);
    float4 gg = ((const float4*)g)[tid];
    float4 bb = ((const float4*)b)[tid];
    float r0 = dx*rs*gg.x + bb.x, r1 = dy*rs*gg.y + bb.y;
    float r2 = dz*rs*gg.z + bb.z, r3 = dw*rs*gg.w + bb.w;
    float h0 = __bfloat162float(__float2bfloat16(r0));
    float h1 = __bfloat162float(__float2bfloat16(r1));
    float h2 = __bfloat162float(__float2bfloat16(r2));
    float h3 = __bfloat162float(__float2bfloat16(r3));
    size_t o = (size_t)n * EMB + tid * 4;
    *(uint2*)(oh + o) = make_uint2(pack_bf2(r0, r1), pack_bf2(r2, r3));
    *(uint2*)(ol + o) = make_uint2(pack_bf2(r0 - h0, r1 - h1), pack_bf2(r2 - h2, r3 - h3));
}

// =================== 4-stage cp.async split-bf16 MMA GEMM ====================
// A: hi/lo bf16 [M][K], B: hi/lo bf16 [N][K]. 128x128 CTA, BK=32, 8 warps.
// Per-stage smem: A[128][128B] (hi ch0-3 | lo ch4-7, swizzled) + B same = 32KB.
#define FLAG_BIAS 1
#define FLAG_GELU 2
#define FLAG_RES  4
#define FLAG_OSPL 8
#define MG_SMEM (4 * 32768)

__global__ __launch_bounds__(256, 1) void mgemm3_kernel(
    const bf16* __restrict__ Ah, const bf16* __restrict__ Al,
    const bf16* __restrict__ Bh, const bf16* __restrict__ Bl,
    const float* __restrict__ bias, const float* __restrict__ res,
    float* __restrict__ C, bf16* __restrict__ Oh, bf16* __restrict__ Ol,
    int M, int N, int K, int flags) {
    extern __shared__ char sm[];
    uint32_t smb = smem_u32(sm);

    int tid = threadIdx.x;
    int lane = tid & 31, wid = tid >> 5;
    int warp_m = wid >> 2, warp_n = wid & 3;
    int rowBase = blockIdx.x * 128, colBase = blockIdx.y * 128;

    float acc[4][4][4];
    #pragma unroll
    for (int i = 0; i < 4; i++)
        #pragma unroll
        for (int j = 0; j < 4; j++)
            #pragma unroll
            for (int q = 0; q < 4; q++) acc[i][j][q] = 0.0f;

    int S = K >> 5;
    int r0 = tid >> 1;                 // A/B row pairs: 2 chunks per thread per op
    int c0 = (tid & 1) * 4;           // chunk base 0 or 4 -> handles 2 chunks each? no:

    // per thread: 4 A-chunks + 4 B-chunks per stage (1024 chunks per operand /256)
    auto load_stage = [&](int s, int buf) {
        uint32_t sb = smb + buf * 32768;
        const bf16* gAh = Ah + (size_t)rowBase * K + s * 32;
        const bf16* gAl = Al + (size_t)rowBase * K + s * 32;
        const bf16* gBh = Bh + (size_t)colBase * K + s * 32;
        const bf16* gBl = Bl + (size_t)colBase * K + s * 32;
        #pragma unroll
        for (int i = 0; i < 4; i++) {
            int f = tid + i * 256;          // 0..1023
            int r = f >> 3, c = f & 7;      // row 0..127, chunk 0..7
            uint32_t so = (uint32_t)(r * 128 + ((c ^ (r & 7)) * 16));
            const bf16* srcA = (c < 4) ? (gAh + (size_t)r * K + c * 8)
                                       : (gAl + (size_t)r * K + (c - 4) * 8);
            const bf16* srcB = (c < 4) ? (gBh + (size_t)r * K + c * 8)
                                       : (gBl + (size_t)r * K + (c - 4) * 8);
            cpa16(sb + so, srcA);
            cpa16(sb + 16384 + so, srcB);
        }
        CPA_COMMIT();
    };

    load_stage(0, 0);
    load_stage(1, 1);
    load_stage(2, 2);

    for (int s = 0; s < S; ++s) {
        int buf = s & 3;
        CPA_WAIT2();
        __syncthreads();
        if (s + 3 < S) load_stage(s + 3, (s + 3) & 3);
        else CPA_COMMIT();

        uint32_t As = smb + buf * 32768;
        uint32_t Bs = As + 16384;

        #pragma unroll
        for (int kk = 0; kk < 2; ++kk) {
            uint32_t ah[4][4], al[4][4];
            #pragma unroll
            for (int mt = 0; mt < 4; ++mt) {
                int r = warp_m * 64 + mt * 16 + (lane & 15);
                int ch = kk * 2 + (lane >> 4);
                LDSM4(ah[mt], As + (uint32_t)(r * 128 + ((ch ^ (r & 7)) * 16)));
                LDSM4(al[mt], As + (uint32_t)(r * 128 + (((ch + 4) ^ (r & 7)) * 16)));
            }
            uint32_t bh[8], bl[8];
            #pragma unroll
            for (int g2 = 0; g2 < 2; ++g2) {
                int n = warp_n * 32 + g2 * 16 + ((lane >> 4) << 3) + (lane & 7);
                int ch = kk * 2 + ((lane >> 3) & 1);
                LDSM4(&bh[g2 * 4], Bs + (uint32_t)(n * 128 + ((ch ^ (n & 7)) * 16)));
                LDSM4(&bl[g2 * 4], Bs + (uint32_t)(n * 128 + (((ch + 4) ^ (n & 7)) * 16)));
            }
            #pragma unroll
            for (int mt = 0; mt < 4; ++mt)
                #pragma unroll
                for (int nt = 0; nt < 4; ++nt) {
                    uint32_t* ph = &bh[(nt >> 1) * 4 + (nt & 1) * 2];
                    uint32_t* pl = &bl[(nt >> 1) * 4 + (nt & 1) * 2];
                    MMA16816(acc[mt][nt], ah[mt], ph);
                    MMA16816(acc[mt][nt], ah[mt], pl);
                    MMA16816(acc[mt][nt], al[mt], ph);
                }
        }
        __syncthreads();
    }

    // ---- epilogue ----
    #pragma unroll
    for (int mt = 0; mt < 4; ++mt) {
        #pragma unroll
        for (int nt = 0; nt < 4; ++nt) {
            int col = colBase + warp_n * 32 + nt * 8 + (lane & 3) * 2;
            int row0 = rowBase + warp_m * 64 + mt * 16 + (lane >> 2);
            #pragma unroll
            for (int half = 0; half < 2; ++half) {
                size_t row = (size_t)(row0 + half * 8);
                float v0 = acc[mt][nt][half * 2 + 0];
                float v1 = acc[mt][nt][half * 2 + 1];
                if (flags & FLAG_BIAS) { v0 += bias[col]; v1 += bias[col + 1]; }
                if (flags & FLAG_GELU) {
                    v0 = 0.5f * v0 * (1.0f + erff(v0 * 0.70710678118654752f));
                    v1 = 0.5f * v1 * (1.0f + erff(v1 * 0.70710678118654752f));
                }
                if (flags & FLAG_RES) {
                    float2 rv = *(const float2*)(res + row * N + col);
                    v0 += rv.x; v1 += rv.y;
                }
                if (flags & FLAG_OSPL) {
                    float h0 = __bfloat162float(__float2bfloat16(v0));
                    float h1 = __bfloat162float(__float2bfloat16(v1));
                    *(uint32_t*)(Oh + row * N + col) = pack_bf2(v0, v1);
                    *(uint32_t*)(Ol + row * N + col) = pack_bf2(v0 - h0, v1 - h1);
                } else {
                    *(float2*)(C + row * N + col) = make_float2(v0, v1);
                }
            }
        }
    }
}

// =================== flash attention (register-tiled fp32) ===================
// qkv: [NTOK][3072] fused (q | k | v). Output hi/lo bf16 [NTOK][1024].
#define FA_SMEM (4 * 64 * 68 * 4)
#define QKVS 3072

__global__ __launch_bounds__(128) void fattn_kernel(
    const float* __restrict__ qkv, bf16* __restrict__ oh, bf16* __restrict__ ol) {
    extern __shared__ float smf[];
    float* Qs = smf;
    float* Ks = smf + 64 * 68;
    float* Vs = smf + 2 * 64 * 68;
    float* Ps = smf + 3 * 64 * 68;

    int qt = gridDim.x - 1 - blockIdx.x;    // long blocks first
    int bh = blockIdx.y;
    int b = bh >> 4, h = bh & 15;
    size_t base = (size_t)(b * SEQ) * QKVS + h * HD;
    int qBase = qt * 64;
    int tid = threadIdx.x;
    int ty = tid >> 3, tx = tid & 7;

    #pragma unroll
    for (int j = 0; j < 8; ++j) {
        int f = tid + j * 128;
        int rr = f >> 4, d4 = f & 15;
        *(float4*)(Qs + rr * 68 + d4 * 4) =
            *(const float4*)(qkv + base + (size_t)(qBase + rr) * QKVS + d4 * 4);
    }

    float m[4], l[4], acc[4][8];
    #pragma unroll
    for (int i = 0; i < 4; ++i) {
        m[i] = -1e30f; l[i] = 0.0f;
        #pragma unroll
        for (int j = 0; j < 8; ++j) acc[i][j] = 0.0f;
    }

    for (int kt = 0; kt <= qt; ++kt) {
        int kBase = kt * 64;
        __syncthreads();
        #pragma unroll
        for (int j = 0; j < 8; ++j) {
            int f = tid + j * 128;
            int rr = f >> 4, d4 = f & 15;
            *(float4*)(Ks + rr * 68 + d4 * 4) =
                *(const float4*)(qkv + base + 1024 + (size_t)(kBase + rr) * QKVS + d4 * 4);
            *(float4*)(Vs + rr * 68 + d4 * 4) =
                *(const float4*)(qkv + base + 2048 + (size_t)(kBase + rr) * QKVS + d4 * 4);
        }
        __syncthreads();

        float s[4][8];
        #pragma unroll
        for (int i = 0; i < 4; ++i)
            #pragma unroll
            for (int j = 0; j < 8; ++j) s[i][j] = 0.0f;

        #pragma unroll
        for (int d4 = 0; d4 < 16; ++d4) {
            float4 qv[4];
            #pragma unroll
            for (int i = 0; i < 4; ++i)
                qv[i] = *(const float4*)(Qs + (ty + 16 * i) * 68 + d4 * 4);
            #pragma unroll
            for (int j = 0; j < 8; ++j) {
                float4 kv = *(const float4*)(Ks + (tx * 8 + j) * 68 + d4 * 4);
                #pragma unroll
                for (int i = 0; i < 4; ++i) {
                    s[i][j] = fmaf(qv[i].x, kv.x, s[i][j]);
                    s[i][j] = fmaf(qv[i].y, kv.y, s[i][j]);
                    s[i][j] = fmaf(qv[i].z, kv.z, s[i][j]);
                    s[i][j] = fmaf(qv[i].w, kv.w, s[i][j]);
                }
            }
        }

        bool diag = (kt == qt);
        #pragma unroll
        for (int i = 0; i < 4; ++i) {
            int R = ty + 16 * i;
            float mx = -1e30f;
            #pragma unroll
            for (int j = 0; j < 8; ++j) {
                float sv = s[i][j] * 0.125f;
                if (diag && (tx * 8 + j > R)) sv = -1e30f;
                s[i][j] = sv;
                mx = fmaxf(mx, sv);
            }
            mx = fmaxf(mx, __shfl_xor_sync(0xffffffffu, mx, 1));
            mx = fmaxf(mx, __shfl_xor_sync(0xffffffffu, mx, 2));
            mx = fmaxf(mx, __shfl_xor_sync(0xffffffffu, mx, 4));
            float mnew = fmaxf(m[i], mx);
            float corr = __expf(m[i] - mnew);
            float p[8], psum = 0.0f;
            #pragma unroll
            for (int j = 0; j < 8; ++j) { p[j] = __expf(s[i][j] - mnew); psum += p[j]; }
            *(float4*)(Ps + R * 68 + tx * 8)     = make_float4(p[0], p[1], p[2], p[3]);
            *(float4*)(Ps + R * 68 + tx * 8 + 4) = make_float4(p[4], p[5], p[6], p[7]);
            psum += __shfl_xor_sync(0xffffffffu, psum, 1);
            psum += __shfl_xor_sync(0xffffffffu, psum, 2);
            psum += __shfl_xor_sync(0xffffffffu, psum, 4);
            l[i] = l[i] * corr + psum;
            m[i] = mnew;
            #pragma unroll
            for (int j = 0; j < 8; ++j) acc[i][j] *= corr;
        }
        __syncwarp();

        #pragma unroll
        for (int s4 = 0; s4 < 16; ++s4) {
            float4 pv[4];
            #pragma unroll
            for (int i = 0; i < 4; ++i)
                pv[i] = *(const float4*)(Ps + (ty + 16 * i) * 68 + s4 * 4);
            #pragma unroll
            for (int ss = 0; ss < 4; ++ss) {
                const float* vr = Vs + (s4 * 4 + ss) * 68 + tx * 8;
                float4 v0 = *(const float4*)(vr);
                float4 v1 = *(const float4*)(vr + 4);
                #pragma unroll
                for (int i = 0; i < 4; ++i) {
                    float p = (ss == 0) ? pv[i].x : (ss == 1) ? pv[i].y :
                              (ss == 2) ? pv[i].z : pv[i].w;
                    acc[i][0] = fmaf(p, v0.x, acc[i][0]);
                    acc[i][1] = fmaf(p, v0.y, acc[i][1]);
                    acc[i][2] = fmaf(p, v0.z, acc[i][2]);
                    acc[i][3] = fmaf(p, v0.w, acc[i][3]);
                    acc[i][4] = fmaf(p, v1.x, acc[i][4]);
                    acc[i][5] = fmaf(p, v1.y, acc[i][5]);
                    acc[i][6] = fmaf(p, v1.z, acc[i][6]);
                    acc[i][7] = fmaf(p, v1.w, acc[i][7]);
                }
            }
        }
        __syncwarp();
    }

    #pragma unroll
    for (int i = 0; i < 4; ++i) {
        float inv = 1.0f / l[i];
        size_t off = (size_t)(b * SEQ + qBase + ty + 16 * i) * EMB + h * HD + tx * 8;
        #pragma unroll
        for (int j = 0; j < 8; j += 2) {
            float v0 = acc[i][j] * inv, v1 = acc[i][j + 1] * inv;
            float h0 = __bfloat162float(__float2bfloat16(v0));
            float h1 = __bfloat162float(__float2bfloat16(v1));
            *(uint32_t*)(oh + off + j) = pack_bf2(v0, v1);
            *(uint32_t*)(ol + off + j) = pack_bf2(v0 - h0, v1 - h1);
        }
    }
}

// ---------------- launch ----------------------------------------------------
extern "C" void kernel_launch(void* const* d_in, const int* in_sizes, int n_in,
                              void* d_out, int out_size) {
    const int*   idx    = (const int*)d_in[0];
    const float* tok    = (const float*)d_in[1];
    const float* pos    = (const float*)d_in[2];
    const float* Wq     = (const float*)d_in[3];
    const float* Wk     = (const float*)d_in[4];
    const float* Wv     = (const float*)d_in[5];
    const float* Wp     = (const float*)d_in[6];
    const float* bp     = (const float*)d_in[7];
    const float* ln1_g  = (const float*)d_in[8];
    const float* ln1_b  = (const float*)d_in[9];
    const float* ln2_g  = (const float*)d_in[10];
    const float* ln2_b  = (const float*)d_in[11];
    const float* W1     = (const float*)d_in[12];
    const float* b1     = (const float*)d_in[13];
    const float* W2     = (const float*)d_in[14];
    const float* b2     = (const float*)d_in[15];
    const float* lnf_g  = (const float*)d_in[16];
    const float* lnf_b  = (const float*)d_in[17];
    const float* Wout   = (const float*)d_in[18];

    float *x, *qkv;
    bf16 *hh, *hl, *ohh, *ohl, *uh, *ul;
    bf16 *wqkvh, *wqkvl, *wph, *wpl, *w1h, *w1l, *w2h, *w2l, *woh, *wol;
    cudaGetSymbolAddress((void**)&x, g_x);
    cudaGetSymbolAddress((void**)&qkv, g_qkv);
    cudaGetSymbolAddress((void**)&hh, g_h_h);
    cudaGetSymbolAddress((void**)&hl, g_h_l);
    cudaGetSymbolAddress((void**)&ohh, g_o_h);
    cudaGetSymbolAddress((void**)&ohl, g_o_l);
    cudaGetSymbolAddress((void**)&uh, g_u_h);
    cudaGetSymbolAddress((void**)&ul, g_u_l);
    cudaGetSymbolAddress((void**)&wqkvh, g_Wqkv_h); cudaGetSymbolAddress((void**)&wqkvl, g_Wqkv_l);
    cudaGetSymbolAddress((void**)&wph, g_Wp_h);     cudaGetSymbolAddress((void**)&wpl, g_Wp_l);
    cudaGetSymbolAddress((void**)&w1h, g_W1_h);     cudaGetSymbolAddress((void**)&w1l, g_W1_l);
    cudaGetSymbolAddress((void**)&w2h, g_W2_h);     cudaGetSymbolAddress((void**)&w2l, g_W2_l);
    cudaGetSymbolAddress((void**)&woh, g_Wo_h);     cudaGetSymbolAddress((void**)&wol, g_Wo_l);

    cudaFuncSetAttribute(mgemm3_kernel, cudaFuncAttributeMaxDynamicSharedMemorySize, MG_SMEM);
    cudaFuncSetAttribute(fattn_kernel, cudaFuncAttributeMaxDynamicSharedMemorySize, FA_SMEM);

    tconv_all<<<130304, dim3(32, 8)>>>(Wq, Wk, Wv, Wp, W1, W2, Wout,
                                       wqkvh, wqkvl, wph, wpl, w1h, w1l,
                                       w2h, w2l, woh, wol);
    embed_kernel<<<NTOK, 256>>>(idx, tok, pos, x);

    dim3 gQKV(NTOK / 128, 3 * EMB / 128);  // 32 x 24
    dim3 gE(NTOK / 128, EMB / 128);        // 32 x 8
    dim3 gH(NTOK / 128, HID / 128);        // 32 x 32
    dim3 gV(NTOK / 128, VOCAB / 128);      // 32 x 250
    dim3 gA(SEQ / 64, 2 * NH);             // 32 x 32

    for (int l = 0; l < NL; l++) {
        size_t wo = (size_t)l * EMB * EMB;
        size_t wqo = (size_t)l * 3 * EMB * EMB;
        size_t w1o = (size_t)l * EMB * HID;

        ln_kernel<<<NTOK, 256>>>(x, ln1_g + l * EMB, ln1_b + l * EMB, hh, hl);
        mgemm3_kernel<<<gQKV, 256, MG_SMEM>>>(hh, hl, wqkvh + wqo, wqkvl + wqo,
                                              nullptr, nullptr, qkv, nullptr, nullptr,
                                              NTOK, 3 * EMB, EMB, 0);
        fattn_kernel<<<gA, 128, FA_SMEM>>>(qkv, ohh, ohl);
        mgemm3_kernel<<<gE, 256, MG_SMEM>>>(ohh, ohl, wph + wo, wpl + wo, bp + l * EMB, x,
                                            x, nullptr, nullptr, NTOK, EMB, EMB,
                                            FLAG_BIAS | FLAG_RES);
        ln_kernel<<<NTOK, 256>>>(x, ln2_g + l * EMB, ln2_b + l * EMB, hh, hl);
        mgemm3_kernel<<<gH, 256, MG_SMEM>>>(hh, hl, w1h + w1o, w1l + w1o, b1 + l * HID,
                                            nullptr, nullptr, uh, ul, NTOK, HID, EMB,
                                            FLAG_BIAS | FLAG_GELU | FLAG_OSPL);
        mgemm3_kernel<<<gE, 256, MG_SMEM>>>(uh, ul, w2h + w1o, w2l + w1o, b2 + l * EMB, x,
                                            x, nullptr, nullptr, NTOK, EMB, HID,
                                            FLAG_BIAS | FLAG_RES);
    }

    ln_kernel<<<NTOK, 256>>>(x, lnf_g, lnf_b, hh, hl);
    mgemm3_kernel<<<gV, 256, MG_SMEM>>>(hh, hl, woh, wol, nullptr, nullptr,
                                        (float*)d_out, nullptr, nullptr,
                                        NTOK, VOCAB, EMB, 0);
}

// round 7
// speedup vs baseline: 1.3477x; 1.3477x over previous
#include <cuda_runtime.h>
#include <cuda_bf16.h>
#include <math.h>
#include <stdint.h>

#define NTOK 4096
#define EMB  1024
#define HID  4096
#define VOCAB 32000
#define SEQ  2048
#define NH   16
#define HD   64
#define NL   8

typedef __nv_bfloat16 bf16;
typedef __nv_bfloat162 bf162;

// ---------------- device scratch --------------------------------------------
__device__ __align__(16) float g_x[NTOK * EMB];
__device__ __align__(16) float g_qkv[NTOK * 3 * EMB];

__device__ __align__(16) bf16 g_h_h[NTOK * EMB];
__device__ __align__(16) bf16 g_h_l[NTOK * EMB];
__device__ __align__(16) bf16 g_o_h[NTOK * EMB];
__device__ __align__(16) bf16 g_o_l[NTOK * EMB];
__device__ __align__(16) bf16 g_u_h[NTOK * HID];
__device__ __align__(16) bf16 g_u_l[NTOK * HID];

// transposed weights [N][K] hi/lo; QKV fused to [3E][E] per layer
__device__ __align__(16) bf16 g_Wqkv_h[NL * 3 * EMB * EMB];
__device__ __align__(16) bf16 g_Wqkv_l[NL * 3 * EMB * EMB];
__device__ __align__(16) bf16 g_Wp_h[NL * EMB * EMB];
__device__ __align__(16) bf16 g_Wp_l[NL * EMB * EMB];
__device__ __align__(16) bf16 g_W1_h[NL * EMB * HID];
__device__ __align__(16) bf16 g_W1_l[NL * EMB * HID];
__device__ __align__(16) bf16 g_W2_h[NL * EMB * HID];
__device__ __align__(16) bf16 g_W2_l[NL * EMB * HID];
__device__ __align__(16) bf16 g_Wo_h[(size_t)VOCAB * EMB];
__device__ __align__(16) bf16 g_Wo_l[(size_t)VOCAB * EMB];

// ---------------- helpers ---------------------------------------------------
__device__ __forceinline__ uint32_t smem_u32(const void* p) {
    return (uint32_t)__cvta_generic_to_shared((void*)p);
}
__device__ __forceinline__ uint32_t pack_bf2(float a, float b) {
    bf162 t = __floats2bfloat162_rn(a, b);
    return *reinterpret_cast<uint32_t*>(&t);
}
__device__ __forceinline__ void cpa16(uint32_t dst, const void* src) {
    asm volatile("cp.async.ca.shared.global [%0], [%1], 16;" :: "r"(dst), "l"(src));
}
#define CPA_COMMIT() asm volatile("cp.async.commit_group;" ::: "memory")
#define CPA_WAIT2()  asm volatile("cp.async.wait_group 2;" ::: "memory")

#define LDSM4(r, a) \
    asm volatile("ldmatrix.sync.aligned.m8n8.x4.shared.b16 {%0,%1,%2,%3}, [%4];" \
        : "=r"((r)[0]), "=r"((r)[1]), "=r"((r)[2]), "=r"((r)[3]) : "r"(a))

#define MMA16816(d, a, b) \
    asm volatile("mma.sync.aligned.m16n8k16.row.col.f32.bf16.bf16.f32 " \
        "{%0,%1,%2,%3},{%4,%5,%6,%7},{%8,%9},{%0,%1,%2,%3};" \
        : "+f"((d)[0]), "+f"((d)[1]), "+f"((d)[2]), "+f"((d)[3]) \
        : "r"((a)[0]), "r"((a)[1]), "r"((a)[2]), "r"((a)[3]), \
          "r"((b)[0]), "r"((b)[1]))

// ---------------- all-weights transpose + split-convert ----------------------
__global__ void tconv_all(const float* __restrict__ Wq, const float* __restrict__ Wk,
                          const float* __restrict__ Wv, const float* __restrict__ Wp,
                          const float* __restrict__ W1, const float* __restrict__ W2,
                          const float* __restrict__ Wout,
                          bf16* __restrict__ qkvh, bf16* __restrict__ qkvl,
                          bf16* __restrict__ wph, bf16* __restrict__ wpl,
                          bf16* __restrict__ w1h, bf16* __restrict__ w1l,
                          bf16* __restrict__ w2h, bf16* __restrict__ w2l,
                          bf16* __restrict__ woh, bf16* __restrict__ wol) {
    __shared__ float t[32][33];
    int b = blockIdx.x;
    const float* src; bf16 *oh, *ol;
    int K, N, tilesX, tloc, rowOff = 0;

    if (b < 24576) {
        int type = b / 8192, lb = b % 8192;
        int layer = lb / 1024; tloc = lb % 1024;
        K = 1024; N = 1024; tilesX = 32;
        src = (type == 0 ? Wq : type == 1 ? Wk : Wv) + (size_t)layer * EMB * EMB;
        oh = qkvh + (size_t)layer * 3 * EMB * EMB;
        ol = qkvl + (size_t)layer * 3 * EMB * EMB;
        rowOff = type * 1024;
    } else if (b < 32768) {
        int lb = b - 24576;
        int layer = lb / 1024; tloc = lb % 1024;
        K = 1024; N = 1024; tilesX = 32;
        src = Wp + (size_t)layer * EMB * EMB;
        oh = wph + (size_t)layer * EMB * EMB;
        ol = wpl + (size_t)layer * EMB * EMB;
    } else if (b < 65536) {
        int lb = b - 32768;
        int layer = lb / 4096; tloc = lb % 4096;
        K = 1024; N = 4096; tilesX = 128;
        src = W1 + (size_t)layer * EMB * HID;
        oh = w1h + (size_t)layer * EMB * HID;
        ol = w1l + (size_t)layer * EMB * HID;
    } else if (b < 98304) {
        int lb = b - 65536;
        int layer = lb / 4096; tloc = lb % 4096;
        K = 4096; N = 1024; tilesX = 32;
        src = W2 + (size_t)layer * HID * EMB;
        oh = w2h + (size_t)layer * HID * EMB;
        ol = w2l + (size_t)layer * HID * EMB;
    } else {
        tloc = b - 98304;
        K = 1024; N = VOCAB; tilesX = 1000;
        src = Wout; oh = woh; ol = wol;
    }

    int bx = (tloc % tilesX) * 32;
    int by = (tloc / tilesX) * 32;
    int x = threadIdx.x, y = threadIdx.y;
    #pragma unroll
    for (int i = 0; i < 4; i++)
        t[y + i * 8][x] = src[(size_t)(by + y + i * 8) * N + bx + x];
    __syncthreads();
    #pragma unroll
    for (int i = 0; i < 4; i++) {
        int n = bx + y + i * 8, k = by + x;
        float v = t[x][y + i * 8];
        bf16 hv = __float2bfloat16(v);
        oh[(size_t)(rowOff + n) * K + k] = hv;
        ol[(size_t)(rowOff + n) * K + k] = __float2bfloat16(v - __bfloat162float(hv));
    }
}

// ---------------- embed ------------------------------------------------------
__global__ void embed_kernel(const int* __restrict__ idx, const float* __restrict__ tok,
                             const float* __restrict__ pos, float* __restrict__ x) {
    int n = blockIdx.x, e4 = threadIdx.x, t = n & (SEQ - 1);
    float4 a = ((const float4*)(tok + (size_t)idx[n] * EMB))[e4];
    float4 b = ((const float4*)(pos + (size_t)t * EMB))[e4];
    a.x += b.x; a.y += b.y; a.z += b.z; a.w += b.w;
    ((float4*)(x + (size_t)n * EMB))[e4] = a;
}

// ---------------- layernorm -> hi/lo bf16 ------------------------------------
__device__ __forceinline__ float block_sum_256(float s, float* red) {
    #pragma unroll
    for (int o = 16; o; o >>= 1) s += __shfl_xor_sync(0xffffffffu, s, o);
    if ((threadIdx.x & 31) == 0) red[threadIdx.x >> 5] = s;
    __syncthreads();
    if (threadIdx.x < 32) {
        float t = (threadIdx.x < 8) ? red[threadIdx.x] : 0.0f;
        #pragma unroll
        for (int o = 4; o; o >>= 1) t += __shfl_xor_sync(0xffffffffu, t, o);
        if (threadIdx.x == 0) red[0] = t;
    }
    __syncthreads();
    float r = red[0];
    __syncthreads();
    return r;
}

__global__ void ln_kernel(const float* __restrict__ x, const float* __restrict__ g,
                          const float* __restrict__ b, bf16* __restrict__ oh,
                          bf16* __restrict__ ol) {
    __shared__ float red[8];
    int n = blockIdx.x, tid = threadIdx.x;
    float4 v = ((const float4*)(x + (size_t)n * EMB))[tid];
    float mu = block_sum_256(v.x + v.y + v.z + v.w, red) * (1.0f / EMB);
    float dx = v.x - mu, dy = v.y - mu, dz = v.z - mu, dw = v.w - mu;
    float var = block_sum_256(dx*dx + dy*dy + dz*dz + dw*dw, red) * (1.0f / EMB);
    float rs = rsqrtf(var + 1e-5f);
    float4 gg = ((const float4*)g)[tid];
    float4 bb = ((const float4*)b)[tid];
    float r0 = dx*rs*gg.x + bb.x, r1 = dy*rs*gg.y + bb.y;
    float r2 = dz*rs*gg.z + bb.z, r3 = dw*rs*gg.w + bb.w;
    float h0 = __bfloat162float(__float2bfloat16(r0));
    float h1 = __bfloat162float(__float2bfloat16(r1));
    float h2 = __bfloat162float(__float2bfloat16(r2));
    float h3 = __bfloat162float(__float2bfloat16(r3));
    size_t o = (size_t)n * EMB + tid * 4;
    *(uint2*)(oh + o) = make_uint2(pack_bf2(r0, r1), pack_bf2(r2, r3));
    *(uint2*)(ol + o) = make_uint2(pack_bf2(r0 - h0, r1 - h1), pack_bf2(r2 - h2, r3 - h3));
}

// =================== 16-warp cp.async split-bf16 MMA GEMM ====================
// 128x128 CTA, BK=32, 512 threads, 16 warps (4x4), warp tile 32x32, 4-stage ring.
#define FLAG_BIAS 1
#define FLAG_GELU 2
#define FLAG_RES  4
#define FLAG_OSPL 8
#define MG_SMEM (4 * 32768)

__global__ __launch_bounds__(512, 1) void mgemm4_kernel(
    const bf16* __restrict__ Ah, const bf16* __restrict__ Al,
    const bf16* __restrict__ Bh, const bf16* __restrict__ Bl,
    const float* __restrict__ bias, const float* __restrict__ res,
    float* __restrict__ C, bf16* __restrict__ Oh, bf16* __restrict__ Ol,
    int M, int N, int K, int flags) {
    extern __shared__ char sm[];
    uint32_t smb = smem_u32(sm);

    int tid = threadIdx.x;
    int lane = tid & 31, wid = tid >> 5;
    int warp_m = wid >> 2, warp_n = wid & 3;      // 4 x 4 warps
    int rowBase = blockIdx.x * 128, colBase = blockIdx.y * 128;

    float acc[2][4][4];
    #pragma unroll
    for (int i = 0; i < 2; i++)
        #pragma unroll
        for (int j = 0; j < 4; j++)
            #pragma unroll
            for (int q = 0; q < 4; q++) acc[i][j][q] = 0.0f;

    int S = K >> 5;

    auto load_stage = [&](int s, int buf) {
        uint32_t sb = smb + buf * 32768;
        const bf16* gAh = Ah + (size_t)rowBase * K + s * 32;
        const bf16* gAl = Al + (size_t)rowBase * K + s * 32;
        const bf16* gBh = Bh + (size_t)colBase * K + s * 32;
        const bf16* gBl = Bl + (size_t)colBase * K + s * 32;
        #pragma unroll
        for (int i = 0; i < 2; i++) {
            int f = tid + i * 512;          // 0..1023
            int r = f >> 3, c = f & 7;
            uint32_t so = (uint32_t)(r * 128 + ((c ^ (r & 7)) * 16));
            const bf16* srcA = (c < 4) ? (gAh + (size_t)r * K + c * 8)
                                       : (gAl + (size_t)r * K + (c - 4) * 8);
            const bf16* srcB = (c < 4) ? (gBh + (size_t)r * K + c * 8)
                                       : (gBl + (size_t)r * K + (c - 4) * 8);
            cpa16(sb + so, srcA);
            cpa16(sb + 16384 + so, srcB);
        }
        CPA_COMMIT();
    };

    load_stage(0, 0);
    load_stage(1, 1);
    load_stage(2, 2);

    for (int s = 0; s < S; ++s) {
        int buf = s & 3;
        CPA_WAIT2();
        __syncthreads();
        if (s + 3 < S) load_stage(s + 3, (s + 3) & 3);
        else CPA_COMMIT();

        uint32_t As = smb + buf * 32768;
        uint32_t Bs = As + 16384;

        #pragma unroll
        for (int kk = 0; kk < 2; ++kk) {
            uint32_t ah[2][4], al[2][4];
            #pragma unroll
            for (int mt = 0; mt < 2; ++mt) {
                int r = warp_m * 32 + mt * 16 + (lane & 15);
                int ch = kk * 2 + (lane >> 4);
                LDSM4(ah[mt], As + (uint32_t)(r * 128 + ((ch ^ (r & 7)) * 16)));
                LDSM4(al[mt], As + (uint32_t)(r * 128 + (((ch + 4) ^ (r & 7)) * 16)));
            }
            uint32_t bh[8], bl[8];
            #pragma unroll
            for (int g2 = 0; g2 < 2; ++g2) {
                int n = warp_n * 32 + g2 * 16 + ((lane >> 4) << 3) + (lane & 7);
                int ch = kk * 2 + ((lane >> 3) & 1);
                LDSM4(&bh[g2 * 4], Bs + (uint32_t)(n * 128 + ((ch ^ (n & 7)) * 16)));
                LDSM4(&bl[g2 * 4], Bs + (uint32_t)(n * 128 + (((ch + 4) ^ (n & 7)) * 16)));
            }
            #pragma unroll
            for (int mt = 0; mt < 2; ++mt)
                #pragma unroll
                for (int nt = 0; nt < 4; ++nt) {
                    uint32_t* ph = &bh[(nt >> 1) * 4 + (nt & 1) * 2];
                    uint32_t* pl = &bl[(nt >> 1) * 4 + (nt & 1) * 2];
                    MMA16816(acc[mt][nt], ah[mt], ph);
                    MMA16816(acc[mt][nt], ah[mt], pl);
                    MMA16816(acc[mt][nt], al[mt], ph);
                }
        }
        __syncthreads();
    }

    // ---- epilogue ----
    #pragma unroll
    for (int mt = 0; mt < 2; ++mt) {
        #pragma unroll
        for (int nt = 0; nt < 4; ++nt) {
            int col = colBase + warp_n * 32 + nt * 8 + (lane & 3) * 2;
            int row0 = rowBase + warp_m * 32 + mt * 16 + (lane >> 2);
            #pragma unroll
            for (int half = 0; half < 2; ++half) {
                size_t row = (size_t)(row0 + half * 8);
                float v0 = acc[mt][nt][half * 2 + 0];
                float v1 = acc[mt][nt][half * 2 + 1];
                if (flags & FLAG_BIAS) { v0 += bias[col]; v1 += bias[col + 1]; }
                if (flags & FLAG_GELU) {
                    v0 = 0.5f * v0 * (1.0f + erff(v0 * 0.70710678118654752f));
                    v1 = 0.5f * v1 * (1.0f + erff(v1 * 0.70710678118654752f));
                }
                if (flags & FLAG_RES) {
                    float2 rv = *(const float2*)(res + row * N + col);
                    v0 += rv.x; v1 += rv.y;
                }
                if (flags & FLAG_OSPL) {
                    float h0 = __bfloat162float(__float2bfloat16(v0));
                    float h1 = __bfloat162float(__float2bfloat16(v1));
                    *(uint32_t*)(Oh + row * N + col) = pack_bf2(v0, v1);
                    *(uint32_t*)(Ol + row * N + col) = pack_bf2(v0 - h0, v1 - h1);
                } else {
                    *(float2*)(C + row * N + col) = make_float2(v0, v1);
                }
            }
        }
    }
}

// =================== flash attention (conflict-free K reads) =================
// qkv: [NTOK][3072] fused. Thread (ty,tx) owns rows {ty+16i}, cols {j*8+tx}.
#define FA_SMEM (4 * 64 * 68 * 4)
#define QKVS 3072

__global__ __launch_bounds__(128) void fattn_kernel(
    const float* __restrict__ qkv, bf16* __restrict__ oh, bf16* __restrict__ ol) {
    extern __shared__ float smf[];
    float* Qs = smf;
    float* Ks = smf + 64 * 68;
    float* Vs = smf + 2 * 64 * 68;
    float* Ps = smf + 3 * 64 * 68;

    int qt = gridDim.x - 1 - blockIdx.x;    // long blocks first
    int bh = blockIdx.y;
    int b = bh >> 4, h = bh & 15;
    size_t base = (size_t)(b * SEQ) * QKVS + h * HD;
    int qBase = qt * 64;
    int tid = threadIdx.x;
    int ty = tid >> 3, tx = tid & 7;

    #pragma unroll
    for (int j = 0; j < 8; ++j) {
        int f = tid + j * 128;
        int rr = f >> 4, d4 = f & 15;
        *(float4*)(Qs + rr * 68 + d4 * 4) =
            *(const float4*)(qkv + base + (size_t)(qBase + rr) * QKVS + d4 * 4);
    }

    float m[4], l[4], acc[4][8];
    #pragma unroll
    for (int i = 0; i < 4; ++i) {
        m[i] = -1e30f; l[i] = 0.0f;
        #pragma unroll
        for (int j = 0; j < 8; ++j) acc[i][j] = 0.0f;
    }

    for (int kt = 0; kt <= qt; ++kt) {
        int kBase = kt * 64;
        __syncthreads();
        #pragma unroll
        for (int j = 0; j < 8; ++j) {
            int f = tid + j * 128;
            int rr = f >> 4, d4 = f & 15;
            *(float4*)(Ks + rr * 68 + d4 * 4) =
                *(const float4*)(qkv + base + 1024 + (size_t)(kBase + rr) * QKVS + d4 * 4);
            *(float4*)(Vs + rr * 68 + d4 * 4) =
                *(const float4*)(qkv + base + 2048 + (size_t)(kBase + rr) * QKVS + d4 * 4);
        }
        __syncthreads();

        // scores: thread covers K-cols {j*8+tx}, rows {ty+16i}
        float s[4][8];
        #pragma unroll
        for (int i = 0; i < 4; ++i)
            #pragma unroll
            for (int j = 0; j < 8; ++j) s[i][j] = 0.0f;

        #pragma unroll
        for (int d4 = 0; d4 < 16; ++d4) {
            float4 qv[4];
            #pragma unroll
            for (int i = 0; i < 4; ++i)
                qv[i] = *(const float4*)(Qs + (ty + 16 * i) * 68 + d4 * 4);
            #pragma unroll
            for (int j = 0; j < 8; ++j) {
                float4 kv = *(const float4*)(Ks + (j * 8 + tx) * 68 + d4 * 4);
                #pragma unroll
                for (int i = 0; i < 4; ++i) {
                    s[i][j] = fmaf(qv[i].x, kv.x, s[i][j]);
                    s[i][j] = fmaf(qv[i].y, kv.y, s[i][j]);
                    s[i][j] = fmaf(qv[i].z, kv.z, s[i][j]);
                    s[i][j] = fmaf(qv[i].w, kv.w, s[i][j]);
                }
            }
        }

        bool diag = (kt == qt);
        #pragma unroll
        for (int i = 0; i < 4; ++i) {
            int R = ty + 16 * i;
            float mx = -1e30f;
            #pragma unroll
            for (int j = 0; j < 8; ++j) {
                float sv = s[i][j] * 0.125f;
                if (diag && (j * 8 + tx > R)) sv = -1e30f;
                s[i][j] = sv;
                mx = fmaxf(mx, sv);
            }
            mx = fmaxf(mx, __shfl_xor_sync(0xffffffffu, mx, 1));
            mx = fmaxf(mx, __shfl_xor_sync(0xffffffffu, mx, 2));
            mx = fmaxf(mx, __shfl_xor_sync(0xffffffffu, mx, 4));
            float mnew = fmaxf(m[i], mx);
            float corr = __expf(m[i] - mnew);
            float psum = 0.0f;
            #pragma unroll
            for (int j = 0; j < 8; ++j) {
                float p = __expf(s[i][j] - mnew);
                Ps[R * 68 + j * 8 + tx] = p;
                psum += p;
            }
            psum += __shfl_xor_sync(0xffffffffu, psum, 1);
            psum += __shfl_xor_sync(0xffffffffu, psum, 2);
            psum += __shfl_xor_sync(0xffffffffu, psum, 4);
            l[i] = l[i] * corr + psum;
            m[i] = mnew;
            #pragma unroll
            for (int j = 0; j < 8; ++j) acc[i][j] *= corr;
        }
        __syncwarp();

        #pragma unroll
        for (int s4 = 0; s4 < 16; ++s4) {
            float4 pv[4];
            #pragma unroll
            for (int i = 0; i < 4; ++i)
                pv[i] = *(const float4*)(Ps + (ty + 16 * i) * 68 + s4 * 4);
            #pragma unroll
            for (int ss = 0; ss < 4; ++ss) {
                const float* vr = Vs + (s4 * 4 + ss) * 68 + tx * 8;
                float4 v0 = *(const float4*)(vr);
                float4 v1 = *(const float4*)(vr + 4);
                #pragma unroll
                for (int i = 0; i < 4; ++i) {
                    float p = (ss == 0) ? pv[i].x : (ss == 1) ? pv[i].y :
                              (ss == 2) ? pv[i].z : pv[i].w;
                    acc[i][0] = fmaf(p, v0.x, acc[i][0]);
                    acc[i][1] = fmaf(p, v0.y, acc[i][1]);
                    acc[i][2] = fmaf(p, v0.z, acc[i][2]);
                    acc[i][3] = fmaf(p, v0.w, acc[i][3]);
                    acc[i][4] = fmaf(p, v1.x, acc[i][4]);
                    acc[i][5] = fmaf(p, v1.y, acc[i][5]);
                    acc[i][6] = fmaf(p, v1.z, acc[i][6]);
                    acc[i][7] = fmaf(p, v1.w, acc[i][7]);
                }
            }
        }
        __syncwarp();
    }

    #pragma unroll
    for (int i = 0; i < 4; ++i) {
        float inv = 1.0f / l[i];
        size_t off = (size_t)(b * SEQ + qBase + ty + 16 * i) * EMB + h * HD + tx * 8;
        #pragma unroll
        for (int j = 0; j < 8; j += 2) {
            float v0 = acc[i][j] * inv, v1 = acc[i][j + 1] * inv;
            float h0 = __bfloat162float(__float2bfloat16(v0));
            float h1 = __bfloat162float(__float2bfloat16(v1));
            *(uint32_t*)(oh + off + j) = pack_bf2(v0, v1);
            *(uint32_t*)(ol + off + j) = pack_bf2(v0 - h0, v1 - h1);
        }
    }
}

// ---------------- launch ----------------------------------------------------
extern "C" void kernel_launch(void* const* d_in, const int* in_sizes, int n_in,
                              void* d_out, int out_size) {
    const int*   idx    = (const int*)d_in[0];
    const float* tok    = (const float*)d_in[1];
    const float* pos    = (const float*)d_in[2];
    const float* Wq     = (const float*)d_in[3];
    const float* Wk     = (const float*)d_in[4];
    const float* Wv     = (const float*)d_in[5];
    const float* Wp     = (const float*)d_in[6];
    const float* bp     = (const float*)d_in[7];
    const float* ln1_g  = (const float*)d_in[8];
    const float* ln1_b  = (const float*)d_in[9];
    const float* ln2_g  = (const float*)d_in[10];
    const float* ln2_b  = (const float*)d_in[11];
    const float* W1     = (const float*)d_in[12];
    const float* b1     = (const float*)d_in[13];
    const float* W2     = (const float*)d_in[14];
    const float* b2     = (const float*)d_in[15];
    const float* lnf_g  = (const float*)d_in[16];
    const float* lnf_b  = (const float*)d_in[17];
    const float* Wout   = (const float*)d_in[18];

    float *x, *qkv;
    bf16 *hh, *hl, *ohh, *ohl, *uh, *ul;
    bf16 *wqkvh, *wqkvl, *wph, *wpl, *w1h, *w1l, *w2h, *w2l, *woh, *wol;
    cudaGetSymbolAddress((void**)&x, g_x);
    cudaGetSymbolAddress((void**)&qkv, g_qkv);
    cudaGetSymbolAddress((void**)&hh, g_h_h);
    cudaGetSymbolAddress((void**)&hl, g_h_l);
    cudaGetSymbolAddress((void**)&ohh, g_o_h);
    cudaGetSymbolAddress((void**)&ohl, g_o_l);
    cudaGetSymbolAddress((void**)&uh, g_u_h);
    cudaGetSymbolAddress((void**)&ul, g_u_l);
    cudaGetSymbolAddress((void**)&wqkvh, g_Wqkv_h); cudaGetSymbolAddress((void**)&wqkvl, g_Wqkv_l);
    cudaGetSymbolAddress((void**)&wph, g_Wp_h);     cudaGetSymbolAddress((void**)&wpl, g_Wp_l);
    cudaGetSymbolAddress((void**)&w1h, g_W1_h);     cudaGetSymbolAddress((void**)&w1l, g_W1_l);
    cudaGetSymbolAddress((void**)&w2h, g_W2_h);     cudaGetSymbolAddress((void**)&w2l, g_W2_l);
    cudaGetSymbolAddress((void**)&woh, g_Wo_h);     cudaGetSymbolAddress((void**)&wol, g_Wo_l);

    cudaFuncSetAttribute(mgemm4_kernel, cudaFuncAttributeMaxDynamicSharedMemorySize, MG_SMEM);
    cudaFuncSetAttribute(fattn_kernel, cudaFuncAttributeMaxDynamicSharedMemorySize, FA_SMEM);

    tconv_all<<<130304, dim3(32, 8)>>>(Wq, Wk, Wv, Wp, W1, W2, Wout,
                                       wqkvh, wqkvl, wph, wpl, w1h, w1l,
                                       w2h, w2l, woh, wol);
    embed_kernel<<<NTOK, 256>>>(idx, tok, pos, x);

    dim3 gQKV(NTOK / 128, 3 * EMB / 128);
    dim3 gE(NTOK / 128, EMB / 128);
    dim3 gH(NTOK / 128, HID / 128);
    dim3 gV(NTOK / 128, VOCAB / 128);
    dim3 gA(SEQ / 64, 2 * NH);

    for (int l = 0; l < NL; l++) {
        size_t wo = (size_t)l * EMB * EMB;
        size_t wqo = (size_t)l * 3 * EMB * EMB;
        size_t w1o = (size_t)l * EMB * HID;

        ln_kernel<<<NTOK, 256>>>(x, ln1_g + l * EMB, ln1_b + l * EMB, hh, hl);
        mgemm4_kernel<<<gQKV, 512, MG_SMEM>>>(hh, hl, wqkvh + wqo, wqkvl + wqo,
                                              nullptr, nullptr, qkv, nullptr, nullptr,
                                              NTOK, 3 * EMB, EMB, 0);
        fattn_kernel<<<gA, 128, FA_SMEM>>>(qkv, ohh, ohl);
        mgemm4_kernel<<<gE, 512, MG_SMEM>>>(ohh, ohl, wph + wo, wpl + wo, bp + l * EMB, x,
                                            x, nullptr, nullptr, NTOK, EMB, EMB,
                                            FLAG_BIAS | FLAG_RES);
        ln_kernel<<<NTOK, 256>>>(x, ln2_g + l * EMB, ln2_b + l * EMB, hh, hl);
        mgemm4_kernel<<<gH, 512, MG_SMEM>>>(hh, hl, w1h + w1o, w1l + w1o, b1 + l * HID,
                                            nullptr, nullptr, uh, ul, NTOK, HID, EMB,
                                            FLAG_BIAS | FLAG_GELU | FLAG_OSPL);
        mgemm4_kernel<<<gE, 512, MG_SMEM>>>(uh, ul, w2h + w1o, w2l + w1o, b2 + l * EMB, x,
                                            x, nullptr, nullptr, NTOK, EMB, HID,
                                            FLAG_BIAS | FLAG_RES);
    }

    ln_kernel<<<NTOK, 256>>>(x, lnf_g, lnf_b, hh, hl);
    mgemm4_kernel<<<gV, 512, MG_SMEM>>>(hh, hl, woh, wol, nullptr, nullptr,
                                        (float*)d_out, nullptr, nullptr,
                                        NTOK, VOCAB, EMB, 0);
}

// round 8
// speedup vs baseline: 1.4515x; 1.0771x over previous
#include <cuda_runtime.h>
#include <cuda_bf16.h>
#include <math.h>
#include <stdint.h>

#define NTOK 4096
#define EMB  1024
#define HID  4096
#define VOCAB 32000
#define SEQ  2048
#define NH   16
#define HD   64
#define NL   8

typedef __nv_bfloat16 bf16;
typedef __nv_bfloat162 bf162;

// ---------------- device scratch --------------------------------------------
__device__ __align__(16) float g_x[NTOK * EMB];
__device__ __align__(16) float g_qkv[NTOK * 3 * EMB];

__device__ __align__(16) bf16 g_h_h[NTOK * EMB];
__device__ __align__(16) bf16 g_h_l[NTOK * EMB];
__device__ __align__(16) bf16 g_o_h[NTOK * EMB];
__device__ __align__(16) bf16 g_o_l[NTOK * EMB];
__device__ __align__(16) bf16 g_u_h[NTOK * HID];
__device__ __align__(16) bf16 g_u_l[NTOK * HID];

// transposed weights [N][K] hi/lo; QKV fused to [3E][E] per layer
__device__ __align__(16) bf16 g_Wqkv_h[NL * 3 * EMB * EMB];
__device__ __align__(16) bf16 g_Wqkv_l[NL * 3 * EMB * EMB];
__device__ __align__(16) bf16 g_Wp_h[NL * EMB * EMB];
__device__ __align__(16) bf16 g_Wp_l[NL * EMB * EMB];
__device__ __align__(16) bf16 g_W1_h[NL * EMB * HID];
__device__ __align__(16) bf16 g_W1_l[NL * EMB * HID];
__device__ __align__(16) bf16 g_W2_h[NL * EMB * HID];
__device__ __align__(16) bf16 g_W2_l[NL * EMB * HID];
__device__ __align__(16) bf16 g_Wo_h[(size_t)VOCAB * EMB];
__device__ __align__(16) bf16 g_Wo_l[(size_t)VOCAB * EMB];

// ---------------- helpers ---------------------------------------------------
__device__ __forceinline__ uint32_t smem_u32(const void* p) {
    return (uint32_t)__cvta_generic_to_shared((void*)p);
}
__device__ __forceinline__ uint32_t pack_bf2(float a, float b) {
    bf162 t = __floats2bfloat162_rn(a, b);
    return *reinterpret_cast<uint32_t*>(&t);
}
__device__ __forceinline__ void cpa16(uint32_t dst, const void* src) {
    asm volatile("cp.async.ca.shared.global [%0], [%1], 16;" :: "r"(dst), "l"(src));
}
#define CPA_COMMIT() asm volatile("cp.async.commit_group;" ::: "memory")
#define CPA_WAIT2()  asm volatile("cp.async.wait_group 2;" ::: "memory")

#define LDSM4(r, a) \
    asm volatile("ldmatrix.sync.aligned.m8n8.x4.shared.b16 {%0,%1,%2,%3}, [%4];" \
        : "=r"((r)[0]), "=r"((r)[1]), "=r"((r)[2]), "=r"((r)[3]) : "r"(a))

#define MMA16816(d, a, b) \
    asm volatile("mma.sync.aligned.m16n8k16.row.col.f32.bf16.bf16.f32 " \
        "{%0,%1,%2,%3},{%4,%5,%6,%7},{%8,%9},{%0,%1,%2,%3};" \
        : "+f"((d)[0]), "+f"((d)[1]), "+f"((d)[2]), "+f"((d)[3]) \
        : "r"((a)[0]), "r"((a)[1]), "r"((a)[2]), "r"((a)[3]), \
          "r"((b)[0]), "r"((b)[1]))

// ---------------- all-weights transpose + split-convert ----------------------
__global__ void tconv_all(const float* __restrict__ Wq, const float* __restrict__ Wk,
                          const float* __restrict__ Wv, const float* __restrict__ Wp,
                          const float* __restrict__ W1, const float* __restrict__ W2,
                          const float* __restrict__ Wout,
                          bf16* __restrict__ qkvh, bf16* __restrict__ qkvl,
                          bf16* __restrict__ wph, bf16* __restrict__ wpl,
                          bf16* __restrict__ w1h, bf16* __restrict__ w1l,
                          bf16* __restrict__ w2h, bf16* __restrict__ w2l,
                          bf16* __restrict__ woh, bf16* __restrict__ wol) {
    __shared__ float t[32][33];
    int b = blockIdx.x;
    const float* src; bf16 *oh, *ol;
    int K, N, tilesX, tloc, rowOff = 0;

    if (b < 24576) {
        int type = b / 8192, lb = b % 8192;
        int layer = lb / 1024; tloc = lb % 1024;
        K = 1024; N = 1024; tilesX = 32;
        src = (type == 0 ? Wq : type == 1 ? Wk : Wv) + (size_t)layer * EMB * EMB;
        oh = qkvh + (size_t)layer * 3 * EMB * EMB;
        ol = qkvl + (size_t)layer * 3 * EMB * EMB;
        rowOff = type * 1024;
    } else if (b < 32768) {
        int lb = b - 24576;
        int layer = lb / 1024; tloc = lb % 1024;
        K = 1024; N = 1024; tilesX = 32;
        src = Wp + (size_t)layer * EMB * EMB;
        oh = wph + (size_t)layer * EMB * EMB;
        ol = wpl + (size_t)layer * EMB * EMB;
    } else if (b < 65536) {
        int lb = b - 32768;
        int layer = lb / 4096; tloc = lb % 4096;
        K = 1024; N = 4096; tilesX = 128;
        src = W1 + (size_t)layer * EMB * HID;
        oh = w1h + (size_t)layer * EMB * HID;
        ol = w1l + (size_t)layer * EMB * HID;
    } else if (b < 98304) {
        int lb = b - 65536;
        int layer = lb / 4096; tloc = lb % 4096;
        K = 4096; N = 1024; tilesX = 32;
        src = W2 + (size_t)layer * HID * EMB;
        oh = w2h + (size_t)layer * HID * EMB;
        ol = w2l + (size_t)layer * HID * EMB;
    } else {
        tloc = b - 98304;
        K = 1024; N = VOCAB; tilesX = 1000;
        src = Wout; oh = woh; ol = wol;
    }

    int bx = (tloc % tilesX) * 32;
    int by = (tloc / tilesX) * 32;
    int x = threadIdx.x, y = threadIdx.y;
    #pragma unroll
    for (int i = 0; i < 4; i++)
        t[y + i * 8][x] = src[(size_t)(by + y + i * 8) * N + bx + x];
    __syncthreads();
    #pragma unroll
    for (int i = 0; i < 4; i++) {
        int n = bx + y + i * 8, k = by + x;
        float v = t[x][y + i * 8];
        bf16 hv = __float2bfloat16(v);
        oh[(size_t)(rowOff + n) * K + k] = hv;
        ol[(size_t)(rowOff + n) * K + k] = __float2bfloat16(v - __bfloat162float(hv));
    }
}

// ---------------- embed ------------------------------------------------------
__global__ void embed_kernel(const int* __restrict__ idx, const float* __restrict__ tok,
                             const float* __restrict__ pos, float* __restrict__ x) {
    int n = blockIdx.x, e4 = threadIdx.x, t = n & (SEQ - 1);
    float4 a = ((const float4*)(tok + (size_t)idx[n] * EMB))[e4];
    float4 b = ((const float4*)(pos + (size_t)t * EMB))[e4];
    a.x += b.x; a.y += b.y; a.z += b.z; a.w += b.w;
    ((float4*)(x + (size_t)n * EMB))[e4] = a;
}

// ---------------- layernorm -> hi/lo bf16 ------------------------------------
__device__ __forceinline__ float block_sum_256(float s, float* red) {
    #pragma unroll
    for (int o = 16; o; o >>= 1) s += __shfl_xor_sync(0xffffffffu, s, o);
    if ((threadIdx.x & 31) == 0) red[threadIdx.x >> 5] = s;
    __syncthreads();
    if (threadIdx.x < 32) {
        float t = (threadIdx.x < 8) ? red[threadIdx.x] : 0.0f;
        #pragma unroll
        for (int o = 4; o; o >>= 1) t += __shfl_xor_sync(0xffffffffu, t, o);
        if (threadIdx.x == 0) red[0] = t;
    }
    __syncthreads();
    float r = red[0];
    __syncthreads();
    return r;
}

__global__ void ln_kernel(const float* __restrict__ x, const float* __restrict__ g,
                          const float* __restrict__ b, bf16* __restrict__ oh,
                          bf16* __restrict__ ol) {
    __shared__ float red[8];
    int n = blockIdx.x, tid = threadIdx.x;
    float4 v = ((const float4*)(x + (size_t)n * EMB))[tid];
    float mu = block_sum_256(v.x + v.y + v.z + v.w, red) * (1.0f / EMB);
    float dx = v.x - mu, dy = v.y - mu, dz = v.z - mu, dw = v.w - mu;
    float var = block_sum_256(dx*dx + dy*dy + dz*dz + dw*dw, red) * (1.0f / EMB);
    float rs = rsqrtf(var + 1e-5f);
    float4 gg = ((const float4*)g)[tid];
    float4 bb = ((const float4*)b)[tid];
    float r0 = dx*rs*gg.x + bb.x, r1 = dy*rs*gg.y + bb.y;
    float r2 = dz*rs*gg.z + bb.z, r3 = dw*rs*gg.w + bb.w;
    float h0 = __bfloat162float(__float2bfloat16(r0));
    float h1 = __bfloat162float(__float2bfloat16(r1));
    float h2 = __bfloat162float(__float2bfloat16(r2));
    float h3 = __bfloat162float(__float2bfloat16(r3));
    size_t o = (size_t)n * EMB + tid * 4;
    *(uint2*)(oh + o) = make_uint2(pack_bf2(r0, r1), pack_bf2(r2, r3));
    *(uint2*)(ol + o) = make_uint2(pack_bf2(r0 - h0, r1 - h1), pack_bf2(r2 - h2, r3 - h3));
}

// =================== 16-warp pipelined split-bf16 MMA GEMM ===================
// 128x128 CTA, BK=32, 512 threads, warp tile 32x32, 4-stage cp.async ring,
// register-fragment double buffering (LDSM kk+1 overlaps MMA kk).
#define FLAG_BIAS 1
#define FLAG_GELU 2
#define FLAG_RES  4
#define FLAG_OSPL 8
#define MG_SMEM (4 * 32768)

__global__ __launch_bounds__(512, 1) void mgemm5_kernel(
    const bf16* __restrict__ Ah, const bf16* __restrict__ Al,
    const bf16* __restrict__ Bh, const bf16* __restrict__ Bl,
    const float* __restrict__ bias, const float* __restrict__ res,
    float* __restrict__ C, bf16* __restrict__ Oh, bf16* __restrict__ Ol,
    int M, int N, int K, int flags) {
    extern __shared__ char sm[];
    uint32_t smb = smem_u32(sm);

    int tid = threadIdx.x;
    int lane = tid & 31, wid = tid >> 5;
    int warp_m = wid >> 2, warp_n = wid & 3;
    int rowBase = blockIdx.x * 128, colBase = blockIdx.y * 128;

    float acc[2][4][4];
    #pragma unroll
    for (int i = 0; i < 2; i++)
        #pragma unroll
        for (int j = 0; j < 4; j++)
            #pragma unroll
            for (int q = 0; q < 4; q++) acc[i][j][q] = 0.0f;

    // precomputed LDSM offsets (within a 32KB stage): [kk][slot][hi/lo]
    uint32_t offA[2][2][2], offB[2][2][2];
    #pragma unroll
    for (int kk = 0; kk < 2; ++kk) {
        #pragma unroll
        for (int mt = 0; mt < 2; ++mt) {
            int r = warp_m * 32 + mt * 16 + (lane & 15);
            int ch = kk * 2 + (lane >> 4);
            offA[kk][mt][0] = (uint32_t)(r * 128 + ((ch ^ (r & 7)) * 16));
            offA[kk][mt][1] = (uint32_t)(r * 128 + (((ch + 4) ^ (r & 7)) * 16));
        }
        #pragma unroll
        for (int g2 = 0; g2 < 2; ++g2) {
            int n = warp_n * 32 + g2 * 16 + ((lane >> 4) << 3) + (lane & 7);
            int ch = kk * 2 + ((lane >> 3) & 1);
            offB[kk][g2][0] = (uint32_t)(16384 + n * 128 + ((ch ^ (n & 7)) * 16));
            offB[kk][g2][1] = (uint32_t)(16384 + n * 128 + (((ch + 4) ^ (n & 7)) * 16));
        }
    }

    int S = K >> 5;

    auto load_stage = [&](int s, int buf) {
        uint32_t sb = smb + buf * 32768;
        const bf16* gAh = Ah + (size_t)rowBase * K + s * 32;
        const bf16* gAl = Al + (size_t)rowBase * K + s * 32;
        const bf16* gBh = Bh + (size_t)colBase * K + s * 32;
        const bf16* gBl = Bl + (size_t)colBase * K + s * 32;
        #pragma unroll
        for (int i = 0; i < 2; i++) {
            int f = tid + i * 512;
            int r = f >> 3, c = f & 7;
            uint32_t so = (uint32_t)(r * 128 + ((c ^ (r & 7)) * 16));
            const bf16* srcA = (c < 4) ? (gAh + (size_t)r * K + c * 8)
                                       : (gAl + (size_t)r * K + (c - 4) * 8);
            const bf16* srcB = (c < 4) ? (gBh + (size_t)r * K + c * 8)
                                       : (gBl + (size_t)r * K + (c - 4) * 8);
            cpa16(sb + so, srcA);
            cpa16(sb + 16384 + so, srcB);
        }
        CPA_COMMIT();
    };

    // register frag double buffers
    uint32_t ah[2][2][4], al[2][2][4], bh[2][8], bl[2][8];

    auto ldfrags = [&](int kb, int kk, uint32_t sb) {
        #pragma unroll
        for (int mt = 0; mt < 2; ++mt) {
            LDSM4(ah[kb][mt], sb + offA[kk][mt][0]);
            LDSM4(al[kb][mt], sb + offA[kk][mt][1]);
        }
        #pragma unroll
        for (int g2 = 0; g2 < 2; ++g2) {
            LDSM4(&bh[kb][g2 * 4], sb + offB[kk][g2][0]);
            LDSM4(&bl[kb][g2 * 4], sb + offB[kk][g2][1]);
        }
    };

    auto do_mma = [&](int kb) {
        #pragma unroll
        for (int mt = 0; mt < 2; ++mt)
            #pragma unroll
            for (int nt = 0; nt < 4; ++nt) {
                uint32_t* ph = &bh[kb][(nt >> 1) * 4 + (nt & 1) * 2];
                uint32_t* pl = &bl[kb][(nt >> 1) * 4 + (nt & 1) * 2];
                MMA16816(acc[mt][nt], ah[kb][mt], ph);
                MMA16816(acc[mt][nt], ah[kb][mt], pl);
                MMA16816(acc[kb ? mt : mt][nt], al[kb][mt], ph);
            }
    };

    load_stage(0, 0);
    load_stage(1, 1);
    load_stage(2, 2);

    for (int s = 0; s < S; ++s) {
        int buf = s & 3;
        CPA_WAIT2();
        __syncthreads();
        uint32_t sb = smb + buf * 32768;

        ldfrags(0, 0, sb);                 // frags for kk=0
        if (s + 3 < S) load_stage(s + 3, (s + 3) & 3);
        else CPA_COMMIT();

        ldfrags(1, 1, sb);                 // prefetch kk=1 frags
        do_mma(0);                         // MMA kk=0 (overlaps LDSM above)
        do_mma(1);                         // MMA kk=1
        __syncthreads();
    }

    // ---- epilogue ----
    #pragma unroll
    for (int mt = 0; mt < 2; ++mt) {
        #pragma unroll
        for (int nt = 0; nt < 4; ++nt) {
            int col = colBase + warp_n * 32 + nt * 8 + (lane & 3) * 2;
            int row0 = rowBase + warp_m * 32 + mt * 16 + (lane >> 2);
            #pragma unroll
            for (int half = 0; half < 2; ++half) {
                size_t row = (size_t)(row0 + half * 8);
                float v0 = acc[mt][nt][half * 2 + 0];
                float v1 = acc[mt][nt][half * 2 + 1];
                if (flags & FLAG_BIAS) { v0 += bias[col]; v1 += bias[col + 1]; }
                if (flags & FLAG_GELU) {
                    v0 = 0.5f * v0 * (1.0f + erff(v0 * 0.70710678118654752f));
                    v1 = 0.5f * v1 * (1.0f + erff(v1 * 0.70710678118654752f));
                }
                if (flags & FLAG_RES) {
                    float2 rv = *(const float2*)(res + row * N + col);
                    v0 += rv.x; v1 += rv.y;
                }
                if (flags & FLAG_OSPL) {
                    float h0 = __bfloat162float(__float2bfloat16(v0));
                    float h1 = __bfloat162float(__float2bfloat16(v1));
                    *(uint32_t*)(Oh + row * N + col) = pack_bf2(v0, v1);
                    *(uint32_t*)(Ol + row * N + col) = pack_bf2(v0 - h0, v1 - h1);
                } else {
                    *(float2*)(C + row * N + col) = make_float2(v0, v1);
                }
            }
        }
    }
}

// =================== flash attention (conflict-free K reads) =================
#define FA_SMEM (4 * 64 * 68 * 4)
#define QKVS 3072

__global__ __launch_bounds__(128) void fattn_kernel(
    const float* __restrict__ qkv, bf16* __restrict__ oh, bf16* __restrict__ ol) {
    extern __shared__ float smf[];
    float* Qs = smf;
    float* Ks = smf + 64 * 68;
    float* Vs = smf + 2 * 64 * 68;
    float* Ps = smf + 3 * 64 * 68;

    int qt = gridDim.x - 1 - blockIdx.x;
    int bh = blockIdx.y;
    int b = bh >> 4, h = bh & 15;
    size_t base = (size_t)(b * SEQ) * QKVS + h * HD;
    int qBase = qt * 64;
    int tid = threadIdx.x;
    int ty = tid >> 3, tx = tid & 7;

    #pragma unroll
    for (int j = 0; j < 8; ++j) {
        int f = tid + j * 128;
        int rr = f >> 4, d4 = f & 15;
        *(float4*)(Qs + rr * 68 + d4 * 4) =
            *(const float4*)(qkv + base + (size_t)(qBase + rr) * QKVS + d4 * 4);
    }

    float m[4], l[4], acc[4][8];
    #pragma unroll
    for (int i = 0; i < 4; ++i) {
        m[i] = -1e30f; l[i] = 0.0f;
        #pragma unroll
        for (int j = 0; j < 8; ++j) acc[i][j] = 0.0f;
    }

    for (int kt = 0; kt <= qt; ++kt) {
        int kBase = kt * 64;
        __syncthreads();
        #pragma unroll
        for (int j = 0; j < 8; ++j) {
            int f = tid + j * 128;
            int rr = f >> 4, d4 = f & 15;
            *(float4*)(Ks + rr * 68 + d4 * 4) =
                *(const float4*)(qkv + base + 1024 + (size_t)(kBase + rr) * QKVS + d4 * 4);
            *(float4*)(Vs + rr * 68 + d4 * 4) =
                *(const float4*)(qkv + base + 2048 + (size_t)(kBase + rr) * QKVS + d4 * 4);
        }
        __syncthreads();

        float s[4][8];
        #pragma unroll
        for (int i = 0; i < 4; ++i)
            #pragma unroll
            for (int j = 0; j < 8; ++j) s[i][j] = 0.0f;

        #pragma unroll
        for (int d4 = 0; d4 < 16; ++d4) {
            float4 qv[4];
            #pragma unroll
            for (int i = 0; i < 4; ++i)
                qv[i] = *(const float4*)(Qs + (ty + 16 * i) * 68 + d4 * 4);
            #pragma unroll
            for (int j = 0; j < 8; ++j) {
                float4 kv = *(const float4*)(Ks + (j * 8 + tx) * 68 + d4 * 4);
                #pragma unroll
                for (int i = 0; i < 4; ++i) {
                    s[i][j] = fmaf(qv[i].x, kv.x, s[i][j]);
                    s[i][j] = fmaf(qv[i].y, kv.y, s[i][j]);
                    s[i][j] = fmaf(qv[i].z, kv.z, s[i][j]);
                    s[i][j] = fmaf(qv[i].w, kv.w, s[i][j]);
                }
            }
        }

        bool diag = (kt == qt);
        #pragma unroll
        for (int i = 0; i < 4; ++i) {
            int R = ty + 16 * i;
            float mx = -1e30f;
            #pragma unroll
            for (int j = 0; j < 8; ++j) {
                float sv = s[i][j] * 0.125f;
                if (diag && (j * 8 + tx > R)) sv = -1e30f;
                s[i][j] = sv;
                mx = fmaxf(mx, sv);
            }
            mx = fmaxf(mx, __shfl_xor_sync(0xffffffffu, mx, 1));
            mx = fmaxf(mx, __shfl_xor_sync(0xffffffffu, mx, 2));
            mx = fmaxf(mx, __shfl_xor_sync(0xffffffffu, mx, 4));
            float mnew = fmaxf(m[i], mx);
            float corr = __expf(m[i] - mnew);
            float psum = 0.0f;
            #pragma unroll
            for (int j = 0; j < 8; ++j) {
                float p = __expf(s[i][j] - mnew);
                Ps[R * 68 + j * 8 + tx] = p;
                psum += p;
            }
            psum += __shfl_xor_sync(0xffffffffu, psum, 1);
            psum += __shfl_xor_sync(0xffffffffu, psum, 2);
            psum += __shfl_xor_sync(0xffffffffu, psum, 4);
            l[i] = l[i] * corr + psum;
            m[i] = mnew;
            #pragma unroll
            for (int j = 0; j < 8; ++j) acc[i][j] *= corr;
        }
        __syncwarp();

        #pragma unroll
        for (int s4 = 0; s4 < 16; ++s4) {
            float4 pv[4];
            #pragma unroll
            for (int i = 0; i < 4; ++i)
                pv[i] = *(const float4*)(Ps + (ty + 16 * i) * 68 + s4 * 4);
            #pragma unroll
            for (int ss = 0; ss < 4; ++ss) {
                const float* vr = Vs + (s4 * 4 + ss) * 68 + tx * 8;
                float4 v0 = *(const float4*)(vr);
                float4 v1 = *(const float4*)(vr + 4);
                #pragma unroll
                for (int i = 0; i < 4; ++i) {
                    float p = (ss == 0) ? pv[i].x : (ss == 1) ? pv[i].y :
                              (ss == 2) ? pv[i].z : pv[i].w;
                    acc[i][0] = fmaf(p, v0.x, acc[i][0]);
                    acc[i][1] = fmaf(p, v0.y, acc[i][1]);
                    acc[i][2] = fmaf(p, v0.z, acc[i][2]);
                    acc[i][3] = fmaf(p, v0.w, acc[i][3]);
                    acc[i][4] = fmaf(p, v1.x, acc[i][4]);
                    acc[i][5] = fmaf(p, v1.y, acc[i][5]);
                    acc[i][6] = fmaf(p, v1.z, acc[i][6]);
                    acc[i][7] = fmaf(p, v1.w, acc[i][7]);
                }
            }
        }
        __syncwarp();
    }

    #pragma unroll
    for (int i = 0; i < 4; ++i) {
        float inv = 1.0f / l[i];
        size_t off = (size_t)(b * SEQ + qBase + ty + 16 * i) * EMB + h * HD + tx * 8;
        #pragma unroll
        for (int j = 0; j < 8; j += 2) {
            float v0 = acc[i][j] * inv, v1 = acc[i][j + 1] * inv;
            float h0 = __bfloat162float(__float2bfloat16(v0));
            float h1 = __bfloat162float(__float2bfloat16(v1));
            *(uint32_t*)(oh + off + j) = pack_bf2(v0, v1);
            *(uint32_t*)(ol + off + j) = pack_bf2(v0 - h0, v1 - h1);
        }
    }
}

// ---------------- launch ----------------------------------------------------
extern "C" void kernel_launch(void* const* d_in, const int* in_sizes, int n_in,
                              void* d_out, int out_size) {
    const int*   idx    = (const int*)d_in[0];
    const float* tok    = (const float*)d_in[1];
    const float* pos    = (const float*)d_in[2];
    const float* Wq     = (const float*)d_in[3];
    const float* Wk     = (const float*)d_in[4];
    const float* Wv     = (const float*)d_in[5];
    const float* Wp     = (const float*)d_in[6];
    const float* bp     = (const float*)d_in[7];
    const float* ln1_g  = (const float*)d_in[8];
    const float* ln1_b  = (const float*)d_in[9];
    const float* ln2_g  = (const float*)d_in[10];
    const float* ln2_b  = (const float*)d_in[11];
    const float* W1     = (const float*)d_in[12];
    const float* b1     = (const float*)d_in[13];
    const float* W2     = (const float*)d_in[14];
    const float* b2     = (const float*)d_in[15];
    const float* lnf_g  = (const float*)d_in[16];
    const float* lnf_b  = (const float*)d_in[17];
    const float* Wout   = (const float*)d_in[18];

    float *x, *qkv;
    bf16 *hh, *hl, *ohh, *ohl, *uh, *ul;
    bf16 *wqkvh, *wqkvl, *wph, *wpl, *w1h, *w1l, *w2h, *w2l, *woh, *wol;
    cudaGetSymbolAddress((void**)&x, g_x);
    cudaGetSymbolAddress((void**)&qkv, g_qkv);
    cudaGetSymbolAddress((void**)&hh, g_h_h);
    cudaGetSymbolAddress((void**)&hl, g_h_l);
    cudaGetSymbolAddress((void**)&ohh, g_o_h);
    cudaGetSymbolAddress((void**)&ohl, g_o_l);
    cudaGetSymbolAddress((void**)&uh, g_u_h);
    cudaGetSymbolAddress((void**)&ul, g_u_l);
    cudaGetSymbolAddress((void**)&wqkvh, g_Wqkv_h); cudaGetSymbolAddress((void**)&wqkvl, g_Wqkv_l);
    cudaGetSymbolAddress((void**)&wph, g_Wp_h);     cudaGetSymbolAddress((void**)&wpl, g_Wp_l);
    cudaGetSymbolAddress((void**)&w1h, g_W1_h);     cudaGetSymbolAddress((void**)&w1l, g_W1_l);
    cudaGetSymbolAddress((void**)&w2h, g_W2_h);     cudaGetSymbolAddress((void**)&w2l, g_W2_l);
    cudaGetSymbolAddress((void**)&woh, g_Wo_h);     cudaGetSymbolAddress((void**)&wol, g_Wo_l);

    cudaFuncSetAttribute(mgemm5_kernel, cudaFuncAttributeMaxDynamicSharedMemorySize, MG_SMEM);
    cudaFuncSetAttribute(fattn_kernel, cudaFuncAttributeMaxDynamicSharedMemorySize, FA_SMEM);

    tconv_all<<<130304, dim3(32, 8)>>>(Wq, Wk, Wv, Wp, W1, W2, Wout,
                                       wqkvh, wqkvl, wph, wpl, w1h, w1l,
                                       w2h, w2l, woh, wol);
    embed_kernel<<<NTOK, 256>>>(idx, tok, pos, x);

    dim3 gQKV(NTOK / 128, 3 * EMB / 128);
    dim3 gE(NTOK / 128, EMB / 128);
    dim3 gH(NTOK / 128, HID / 128);
    dim3 gV(NTOK / 128, VOCAB / 128);
    dim3 gA(SEQ / 64, 2 * NH);

    for (int l = 0; l < NL; l++) {
        size_t wo = (size_t)l * EMB * EMB;
        size_t wqo = (size_t)l * 3 * EMB * EMB;
        size_t w1o = (size_t)l * EMB * HID;

        ln_kernel<<<NTOK, 256>>>(x, ln1_g + l * EMB, ln1_b + l * EMB, hh, hl);
        mgemm5_kernel<<<gQKV, 512, MG_SMEM>>>(hh, hl, wqkvh + wqo, wqkvl + wqo,
                                              nullptr, nullptr, qkv, nullptr, nullptr,
                                              NTOK, 3 * EMB, EMB, 0);
        fattn_kernel<<<gA, 128, FA_SMEM>>>(qkv, ohh, ohl);
        mgemm5_kernel<<<gE, 512, MG_SMEM>>>(ohh, ohl, wph + wo, wpl + wo, bp + l * EMB, x,
                                            x, nullptr, nullptr, NTOK, EMB, EMB,
                                            FLAG_BIAS | FLAG_RES);
        ln_kernel<<<NTOK, 256>>>(x, ln2_g + l * EMB, ln2_b + l * EMB, hh, hl);
        mgemm5_kernel<<<gH, 512, MG_SMEM>>>(hh, hl, w1h + w1o, w1l + w1o, b1 + l * HID,
                                            nullptr, nullptr, uh, ul, NTOK, HID, EMB,
                                            FLAG_BIAS | FLAG_GELU | FLAG_OSPL);
        mgemm5_kernel<<<gE, 512, MG_SMEM>>>(uh, ul, w2h + w1o, w2l + w1o, b2 + l * EMB, x,
                                            x, nullptr, nullptr, NTOK, EMB, HID,
                                            FLAG_BIAS | FLAG_RES);
    }

    ln_kernel<<<NTOK, 256>>>(x, lnf_g, lnf_b, hh, hl);
    mgemm5_kernel<<<gV, 512, MG_SMEM>>>(hh, hl, woh, wol, nullptr, nullptr,
                                        (float*)d_out, nullptr, nullptr,
                                        NTOK, VOCAB, EMB, 0);
}

// round 9
// speedup vs baseline: 1.5359x; 1.0581x over previous
#include <cuda_runtime.h>
#include <cuda_bf16.h>
#include <math.h>
#include <stdint.h>

#define NTOK 4096
#define EMB  1024
#define HID  4096
#define VOCAB 32000
#define SEQ  2048
#define NH   16
#define HD   64
#define NL   8

typedef __nv_bfloat16 bf16;
typedef __nv_bfloat162 bf162;

// ---------------- device scratch --------------------------------------------
__device__ __align__(16) float g_x[NTOK * EMB];
__device__ __align__(16) float g_qkv[NTOK * 3 * EMB];

__device__ __align__(16) bf16 g_h_h[NTOK * EMB];
__device__ __align__(16) bf16 g_h_l[NTOK * EMB];
__device__ __align__(16) bf16 g_o_h[NTOK * EMB];
__device__ __align__(16) bf16 g_o_l[NTOK * EMB];
__device__ __align__(16) bf16 g_u_h[NTOK * HID];
__device__ __align__(16) bf16 g_u_l[NTOK * HID];

// transposed weights [N][K] hi/lo; QKV fused to [3E][E] per layer
__device__ __align__(16) bf16 g_Wqkv_h[NL * 3 * EMB * EMB];
__device__ __align__(16) bf16 g_Wqkv_l[NL * 3 * EMB * EMB];
__device__ __align__(16) bf16 g_Wp_h[NL * EMB * EMB];
__device__ __align__(16) bf16 g_Wp_l[NL * EMB * EMB];
__device__ __align__(16) bf16 g_W1_h[NL * EMB * HID];
__device__ __align__(16) bf16 g_W1_l[NL * EMB * HID];
__device__ __align__(16) bf16 g_W2_h[NL * EMB * HID];
__device__ __align__(16) bf16 g_W2_l[NL * EMB * HID];
__device__ __align__(16) bf16 g_Wo_h[(size_t)VOCAB * EMB];
__device__ __align__(16) bf16 g_Wo_l[(size_t)VOCAB * EMB];

// ---------------- helpers ---------------------------------------------------
__device__ __forceinline__ uint32_t smem_u32(const void* p) {
    return (uint32_t)__cvta_generic_to_shared((void*)p);
}
__device__ __forceinline__ uint32_t pack_bf2(float a, float b) {
    bf162 t = __floats2bfloat162_rn(a, b);
    return *reinterpret_cast<uint32_t*>(&t);
}
__device__ __forceinline__ void cpa16(uint32_t dst, const void* src) {
    asm volatile("cp.async.ca.shared.global [%0], [%1], 16;" :: "r"(dst), "l"(src));
}
#define CPA_COMMIT() asm volatile("cp.async.commit_group;" ::: "memory")
#define CPA_WAIT1()  asm volatile("cp.async.wait_group 1;" ::: "memory")

#define LDSM4(r, a) \
    asm volatile("ldmatrix.sync.aligned.m8n8.x4.shared.b16 {%0,%1,%2,%3}, [%4];" \
        : "=r"((r)[0]), "=r"((r)[1]), "=r"((r)[2]), "=r"((r)[3]) : "r"(a))

#define MMA16816(d, a, b) \
    asm volatile("mma.sync.aligned.m16n8k16.row.col.f32.bf16.bf16.f32 " \
        "{%0,%1,%2,%3},{%4,%5,%6,%7},{%8,%9},{%0,%1,%2,%3};" \
        : "+f"((d)[0]), "+f"((d)[1]), "+f"((d)[2]), "+f"((d)[3]) \
        : "r"((a)[0]), "r"((a)[1]), "r"((a)[2]), "r"((a)[3]), \
          "r"((b)[0]), "r"((b)[1]))

// ---------------- all-weights transpose + split-convert ----------------------
__global__ void tconv_all(const float* __restrict__ Wq, const float* __restrict__ Wk,
                          const float* __restrict__ Wv, const float* __restrict__ Wp,
                          const float* __restrict__ W1, const float* __restrict__ W2,
                          const float* __restrict__ Wout,
                          bf16* __restrict__ qkvh, bf16* __restrict__ qkvl,
                          bf16* __restrict__ wph, bf16* __restrict__ wpl,
                          bf16* __restrict__ w1h, bf16* __restrict__ w1l,
                          bf16* __restrict__ w2h, bf16* __restrict__ w2l,
                          bf16* __restrict__ woh, bf16* __restrict__ wol) {
    __shared__ float t[32][33];
    int b = blockIdx.x;
    const float* src; bf16 *oh, *ol;
    int K, N, tilesX, tloc, rowOff = 0;

    if (b < 24576) {
        int type = b / 8192, lb = b % 8192;
        int layer = lb / 1024; tloc = lb % 1024;
        K = 1024; N = 1024; tilesX = 32;
        src = (type == 0 ? Wq : type == 1 ? Wk : Wv) + (size_t)layer * EMB * EMB;
        oh = qkvh + (size_t)layer * 3 * EMB * EMB;
        ol = qkvl + (size_t)layer * 3 * EMB * EMB;
        rowOff = type * 1024;
    } else if (b < 32768) {
        int lb = b - 24576;
        int layer = lb / 1024; tloc = lb % 1024;
        K = 1024; N = 1024; tilesX = 32;
        src = Wp + (size_t)layer * EMB * EMB;
        oh = wph + (size_t)layer * EMB * EMB;
        ol = wpl + (size_t)layer * EMB * EMB;
    } else if (b < 65536) {
        int lb = b - 32768;
        int layer = lb / 4096; tloc = lb % 4096;
        K = 1024; N = 4096; tilesX = 128;
        src = W1 + (size_t)layer * EMB * HID;
        oh = w1h + (size_t)layer * EMB * HID;
        ol = w1l + (size_t)layer * EMB * HID;
    } else if (b < 98304) {
        int lb = b - 65536;
        int layer = lb / 4096; tloc = lb % 4096;
        K = 4096; N = 1024; tilesX = 32;
        src = W2 + (size_t)layer * HID * EMB;
        oh = w2h + (size_t)layer * HID * EMB;
        ol = w2l + (size_t)layer * HID * EMB;
    } else {
        tloc = b - 98304;
        K = 1024; N = VOCAB; tilesX = 1000;
        src = Wout; oh = woh; ol = wol;
    }

    int bx = (tloc % tilesX) * 32;
    int by = (tloc / tilesX) * 32;
    int x = threadIdx.x, y = threadIdx.y;
    #pragma unroll
    for (int i = 0; i < 4; i++)
        t[y + i * 8][x] = src[(size_t)(by + y + i * 8) * N + bx + x];
    __syncthreads();
    #pragma unroll
    for (int i = 0; i < 4; i++) {
        int n = bx + y + i * 8, k = by + x;
        float v = t[x][y + i * 8];
        bf16 hv = __float2bfloat16(v);
        oh[(size_t)(rowOff + n) * K + k] = hv;
        ol[(size_t)(rowOff + n) * K + k] = __float2bfloat16(v - __bfloat162float(hv));
    }
}

// ---------------- embed ------------------------------------------------------
__global__ void embed_kernel(const int* __restrict__ idx, const float* __restrict__ tok,
                             const float* __restrict__ pos, float* __restrict__ x) {
    int n = blockIdx.x, e4 = threadIdx.x, t = n & (SEQ - 1);
    float4 a = ((const float4*)(tok + (size_t)idx[n] * EMB))[e4];
    float4 b = ((const float4*)(pos + (size_t)t * EMB))[e4];
    a.x += b.x; a.y += b.y; a.z += b.z; a.w += b.w;
    ((float4*)(x + (size_t)n * EMB))[e4] = a;
}

// ---------------- layernorm -> hi/lo bf16 ------------------------------------
__device__ __forceinline__ float block_sum_256(float s, float* red) {
    #pragma unroll
    for (int o = 16; o; o >>= 1) s += __shfl_xor_sync(0xffffffffu, s, o);
    if ((threadIdx.x & 31) == 0) red[threadIdx.x >> 5] = s;
    __syncthreads();
    if (threadIdx.x < 32) {
        float t = (threadIdx.x < 8) ? red[threadIdx.x] : 0.0f;
        #pragma unroll
        for (int o = 4; o; o >>= 1) t += __shfl_xor_sync(0xffffffffu, t, o);
        if (threadIdx.x == 0) red[0] = t;
    }
    __syncthreads();
    float r = red[0];
    __syncthreads();
    return r;
}

__global__ void ln_kernel(const float* __restrict__ x, const float* __restrict__ g,
                          const float* __restrict__ b, bf16* __restrict__ oh,
                          bf16* __restrict__ ol) {
    __shared__ float red[8];
    int n = blockIdx.x, tid = threadIdx.x;
    float4 v = ((const float4*)(x + (size_t)n * EMB))[tid];
    float mu = block_sum_256(v.x + v.y + v.z + v.w, red) * (1.0f / EMB);
    float dx = v.x - mu, dy = v.y - mu, dz = v.z - mu, dw = v.w - mu;
    float var = block_sum_256(dx*dx + dy*dy + dz*dz + dw*dw, red) * (1.0f / EMB);
    float rs = rsqrtf(var + 1e-5f);
    float4 gg = ((const float4*)g)[tid];
    float4 bb = ((const float4*)b)[tid];
    float r0 = dx*rs*gg.x + bb.x, r1 = dy*rs*gg.y + bb.y;
    float r2 = dz*rs*gg.z + bb.z, r3 = dw*rs*gg.w + bb.w;
    float h0 = __bfloat162float(__float2bfloat16(r0));
    float h1 = __bfloat162float(__float2bfloat16(r1));
    float h2 = __bfloat162float(__float2bfloat16(r2));
    float h3 = __bfloat162float(__float2bfloat16(r3));
    size_t o = (size_t)n * EMB + tid * 4;
    *(uint2*)(oh + o) = make_uint2(pack_bf2(r0, r1), pack_bf2(r2, r3));
    *(uint2*)(ol + o) = make_uint2(pack_bf2(r0 - h0, r1 - h1), pack_bf2(r2 - h2, r3 - h3));
}

// ============= 16-warp cross-stage-pipelined split-bf16 MMA GEMM =============
// 128x128 CTA, BK=32, 512 threads, warp tile 32x32, 4-stage cp.async ring.
// Fragments for stage s+1 (kk=0) are loaded BEFORE stage s's trailing barrier,
// so every LDSM burst hides under 24 MMAs and the crossbar/tensor overlap.
#define FLAG_BIAS 1
#define FLAG_GELU 2
#define FLAG_RES  4
#define FLAG_OSPL 8
#define MG_SMEM (4 * 32768)

__global__ __launch_bounds__(512, 1) void mgemm6_kernel(
    const bf16* __restrict__ Ah, const bf16* __restrict__ Al,
    const bf16* __restrict__ Bh, const bf16* __restrict__ Bl,
    const float* __restrict__ bias, const float* __restrict__ res,
    float* __restrict__ C, bf16* __restrict__ Oh, bf16* __restrict__ Ol,
    int M, int N, int K, int flags) {
    extern __shared__ char sm[];
    uint32_t smb = smem_u32(sm);

    int tid = threadIdx.x;
    int lane = tid & 31, wid = tid >> 5;
    int warp_m = wid >> 2, warp_n = wid & 3;
    int rowBase = blockIdx.x * 128, colBase = blockIdx.y * 128;

    float acc[2][4][4];
    #pragma unroll
    for (int i = 0; i < 2; i++)
        #pragma unroll
        for (int j = 0; j < 4; j++)
            #pragma unroll
            for (int q = 0; q < 4; q++) acc[i][j][q] = 0.0f;

    // precomputed LDSM offsets within a 32KB stage: [kk][slot][hi/lo]
    uint32_t offA[2][2][2], offB[2][2][2];
    #pragma unroll
    for (int kk = 0; kk < 2; ++kk) {
        #pragma unroll
        for (int mt = 0; mt < 2; ++mt) {
            int r = warp_m * 32 + mt * 16 + (lane & 15);
            int ch = kk * 2 + (lane >> 4);
            offA[kk][mt][0] = (uint32_t)(r * 128 + ((ch ^ (r & 7)) * 16));
            offA[kk][mt][1] = (uint32_t)(r * 128 + (((ch + 4) ^ (r & 7)) * 16));
        }
        #pragma unroll
        for (int g2 = 0; g2 < 2; ++g2) {
            int n = warp_n * 32 + g2 * 16 + ((lane >> 4) << 3) + (lane & 7);
            int ch = kk * 2 + ((lane >> 3) & 1);
            offB[kk][g2][0] = (uint32_t)(16384 + n * 128 + ((ch ^ (n & 7)) * 16));
            offB[kk][g2][1] = (uint32_t)(16384 + n * 128 + (((ch + 4) ^ (n & 7)) * 16));
        }
    }

    int S = K >> 5;

    auto load_stage = [&](int s, int buf) {
        uint32_t sb = smb + buf * 32768;
        const bf16* gAh = Ah + (size_t)rowBase * K + s * 32;
        const bf16* gAl = Al + (size_t)rowBase * K + s * 32;
        const bf16* gBh = Bh + (size_t)colBase * K + s * 32;
        const bf16* gBl = Bl + (size_t)colBase * K + s * 32;
        #pragma unroll
        for (int i = 0; i < 2; i++) {
            int f = tid + i * 512;
            int r = f >> 3, c = f & 7;
            uint32_t so = (uint32_t)(r * 128 + ((c ^ (r & 7)) * 16));
            const bf16* srcA = (c < 4) ? (gAh + (size_t)r * K + c * 8)
                                       : (gAl + (size_t)r * K + (c - 4) * 8);
            const bf16* srcB = (c < 4) ? (gBh + (size_t)r * K + c * 8)
                                       : (gBl + (size_t)r * K + (c - 4) * 8);
            cpa16(sb + so, srcA);
            cpa16(sb + 16384 + so, srcB);
        }
        CPA_COMMIT();
    };

    // register frag double buffers
    uint32_t ah[2][2][4], al[2][2][4], bh[2][8], bl[2][8];

    auto ldfrags = [&](int fb, int kk, uint32_t sb) {
        #pragma unroll
        for (int mt = 0; mt < 2; ++mt) {
            LDSM4(ah[fb][mt], sb + offA[kk][mt][0]);
            LDSM4(al[fb][mt], sb + offA[kk][mt][1]);
        }
        #pragma unroll
        for (int g2 = 0; g2 < 2; ++g2) {
            LDSM4(&bh[fb][g2 * 4], sb + offB[kk][g2][0]);
            LDSM4(&bl[fb][g2 * 4], sb + offB[kk][g2][1]);
        }
    };

    auto do_mma = [&](int fb) {
        #pragma unroll
        for (int mt = 0; mt < 2; ++mt)
            #pragma unroll
            for (int nt = 0; nt < 4; ++nt) {
                uint32_t* ph = &bh[fb][(nt >> 1) * 4 + (nt & 1) * 2];
                uint32_t* pl = &bl[fb][(nt >> 1) * 4 + (nt & 1) * 2];
                MMA16816(acc[mt][nt], ah[fb][mt], ph);
                MMA16816(acc[mt][nt], ah[fb][mt], pl);
                MMA16816(acc[mt][nt], al[fb][mt], ph);
            }
    };

    load_stage(0, 0);
    load_stage(1, 1);
    load_stage(2, 2);
    CPA_WAIT1();                 // buf0, buf1 ready
    __syncthreads();
    ldfrags(0, 0, smb);          // frags for stage 0, kk=0

    for (int s = 0; s < S; ++s) {
        uint32_t sb = smb + (s & 3) * 32768;

        if (s + 3 < S) load_stage(s + 3, (s + 3) & 3);   // overwrites buf (s-1)&3
        else CPA_COMMIT();                                // keep group arithmetic

        ldfrags(1, 1, sb);       // kk=1 frags for this stage
        do_mma(0);               // MMA kk=0 (overlaps LDSM above)

        CPA_WAIT1();             // ensures buf (s+1)&3 data complete
        if (s + 1 < S)
            ldfrags(0, 0, smb + ((s + 1) & 3) * 32768);  // next stage's kk=0 frags
        do_mma(1);               // MMA kk=1 (overlaps LDSM above)
        __syncthreads();
    }

    // ---- epilogue ----
    #pragma unroll
    for (int mt = 0; mt < 2; ++mt) {
        #pragma unroll
        for (int nt = 0; nt < 4; ++nt) {
            int col = colBase + warp_n * 32 + nt * 8 + (lane & 3) * 2;
            int row0 = rowBase + warp_m * 32 + mt * 16 + (lane >> 2);
            #pragma unroll
            for (int half = 0; half < 2; ++half) {
                size_t row = (size_t)(row0 + half * 8);
                float v0 = acc[mt][nt][half * 2 + 0];
                float v1 = acc[mt][nt][half * 2 + 1];
                if (flags & FLAG_BIAS) { v0 += bias[col]; v1 += bias[col + 1]; }
                if (flags & FLAG_GELU) {
                    v0 = 0.5f * v0 * (1.0f + erff(v0 * 0.70710678118654752f));
                    v1 = 0.5f * v1 * (1.0f + erff(v1 * 0.70710678118654752f));
                }
                if (flags & FLAG_RES) {
                    float2 rv = *(const float2*)(res + row * N + col);
                    v0 += rv.x; v1 += rv.y;
                }
                if (flags & FLAG_OSPL) {
                    float h0 = __bfloat162float(__float2bfloat16(v0));
                    float h1 = __bfloat162float(__float2bfloat16(v1));
                    *(uint32_t*)(Oh + row * N + col) = pack_bf2(v0, v1);
                    *(uint32_t*)(Ol + row * N + col) = pack_bf2(v0 - h0, v1 - h1);
                } else {
                    *(float2*)(C + row * N + col) = make_float2(v0, v1);
                }
            }
        }
    }
}

// =================== flash attention (conflict-free K reads) =================
#define FA_SMEM (4 * 64 * 68 * 4)
#define QKVS 3072

__global__ __launch_bounds__(128) void fattn_kernel(
    const float* __restrict__ qkv, bf16* __restrict__ oh, bf16* __restrict__ ol) {
    extern __shared__ float smf[];
    float* Qs = smf;
    float* Ks = smf + 64 * 68;
    float* Vs = smf + 2 * 64 * 68;
    float* Ps = smf + 3 * 64 * 68;

    int qt = gridDim.x - 1 - blockIdx.x;
    int bh = blockIdx.y;
    int b = bh >> 4, h = bh & 15;
    size_t base = (size_t)(b * SEQ) * QKVS + h * HD;
    int qBase = qt * 64;
    int tid = threadIdx.x;
    int ty = tid >> 3, tx = tid & 7;

    #pragma unroll
    for (int j = 0; j < 8; ++j) {
        int f = tid + j * 128;
        int rr = f >> 4, d4 = f & 15;
        *(float4*)(Qs + rr * 68 + d4 * 4) =
            *(const float4*)(qkv + base + (size_t)(qBase + rr) * QKVS + d4 * 4);
    }

    float m[4], l[4], acc[4][8];
    #pragma unroll
    for (int i = 0; i < 4; ++i) {
        m[i] = -1e30f; l[i] = 0.0f;
        #pragma unroll
        for (int j = 0; j < 8; ++j) acc[i][j] = 0.0f;
    }

    for (int kt = 0; kt <= qt; ++kt) {
        int kBase = kt * 64;
        __syncthreads();
        #pragma unroll
        for (int j = 0; j < 8; ++j) {
            int f = tid + j * 128;
            int rr = f >> 4, d4 = f & 15;
            *(float4*)(Ks + rr * 68 + d4 * 4) =
                *(const float4*)(qkv + base + 1024 + (size_t)(kBase + rr) * QKVS + d4 * 4);
            *(float4*)(Vs + rr * 68 + d4 * 4) =
                *(const float4*)(qkv + base + 2048 + (size_t)(kBase + rr) * QKVS + d4 * 4);
        }
        __syncthreads();

        float s[4][8];
        #pragma unroll
        for (int i = 0; i < 4; ++i)
            #pragma unroll
            for (int j = 0; j < 8; ++j) s[i][j] = 0.0f;

        #pragma unroll
        for (int d4 = 0; d4 < 16; ++d4) {
            float4 qv[4];
            #pragma unroll
            for (int i = 0; i < 4; ++i)
                qv[i] = *(const float4*)(Qs + (ty + 16 * i) * 68 + d4 * 4);
            #pragma unroll
            for (int j = 0; j < 8; ++j) {
                float4 kv = *(const float4*)(Ks + (j * 8 + tx) * 68 + d4 * 4);
                #pragma unroll
                for (int i = 0; i < 4; ++i) {
                    s[i][j] = fmaf(qv[i].x, kv.x, s[i][j]);
                    s[i][j] = fmaf(qv[i].y, kv.y, s[i][j]);
                    s[i][j] = fmaf(qv[i].z, kv.z, s[i][j]);
                    s[i][j] = fmaf(qv[i].w, kv.w, s[i][j]);
                }
            }
        }

        bool diag = (kt == qt);
        #pragma unroll
        for (int i = 0; i < 4; ++i) {
            int R = ty + 16 * i;
            float mx = -1e30f;
            #pragma unroll
            for (int j = 0; j < 8; ++j) {
                float sv = s[i][j] * 0.125f;
                if (diag && (j * 8 + tx > R)) sv = -1e30f;
                s[i][j] = sv;
                mx = fmaxf(mx, sv);
            }
            mx = fmaxf(mx, __shfl_xor_sync(0xffffffffu, mx, 1));
            mx = fmaxf(mx, __shfl_xor_sync(0xffffffffu, mx, 2));
            mx = fmaxf(mx, __shfl_xor_sync(0xffffffffu, mx, 4));
            float mnew = fmaxf(m[i], mx);
            float corr = __expf(m[i] - mnew);
            float psum = 0.0f;
            #pragma unroll
            for (int j = 0; j < 8; ++j) {
                float p = __expf(s[i][j] - mnew);
                Ps[R * 68 + j * 8 + tx] = p;
                psum += p;
            }
            psum += __shfl_xor_sync(0xffffffffu, psum, 1);
            psum += __shfl_xor_sync(0xffffffffu, psum, 2);
            psum += __shfl_xor_sync(0xffffffffu, psum, 4);
            l[i] = l[i] * corr + psum;
            m[i] = mnew;
            #pragma unroll
            for (int j = 0; j < 8; ++j) acc[i][j] *= corr;
        }
        __syncwarp();

        #pragma unroll
        for (int s4 = 0; s4 < 16; ++s4) {
            float4 pv[4];
            #pragma unroll
            for (int i = 0; i < 4; ++i)
                pv[i] = *(const float4*)(Ps + (ty + 16 * i) * 68 + s4 * 4);
            #pragma unroll
            for (int ss = 0; ss < 4; ++ss) {
                const float* vr = Vs + (s4 * 4 + ss) * 68 + tx * 8;
                float4 v0 = *(const float4*)(vr);
                float4 v1 = *(const float4*)(vr + 4);
                #pragma unroll
                for (int i = 0; i < 4; ++i) {
                    float p = (ss == 0) ? pv[i].x : (ss == 1) ? pv[i].y :
                              (ss == 2) ? pv[i].z : pv[i].w;
                    acc[i][0] = fmaf(p, v0.x, acc[i][0]);
                    acc[i][1] = fmaf(p, v0.y, acc[i][1]);
                    acc[i][2] = fmaf(p, v0.z, acc[i][2]);
                    acc[i][3] = fmaf(p, v0.w, acc[i][3]);
                    acc[i][4] = fmaf(p, v1.x, acc[i][4]);
                    acc[i][5] = fmaf(p, v1.y, acc[i][5]);
                    acc[i][6] = fmaf(p, v1.z, acc[i][6]);
                    acc[i][7] = fmaf(p, v1.w, acc[i][7]);
                }
            }
        }
        __syncwarp();
    }

    #pragma unroll
    for (int i = 0; i < 4; ++i) {
        float inv = 1.0f / l[i];
        size_t off = (size_t)(b * SEQ + qBase + ty + 16 * i) * EMB + h * HD + tx * 8;
        #pragma unroll
        for (int j = 0; j < 8; j += 2) {
            float v0 = acc[i][j] * inv, v1 = acc[i][j + 1] * inv;
            float h0 = __bfloat162float(__float2bfloat16(v0));
            float h1 = __bfloat162float(__float2bfloat16(v1));
            *(uint32_t*)(oh + off + j) = pack_bf2(v0, v1);
            *(uint32_t*)(ol + off + j) = pack_bf2(v0 - h0, v1 - h1);
        }
    }
}

// ---------------- launch ----------------------------------------------------
extern "C" void kernel_launch(void* const* d_in, const int* in_sizes, int n_in,
                              void* d_out, int out_size) {
    const int*   idx    = (const int*)d_in[0];
    const float* tok    = (const float*)d_in[1];
    const float* pos    = (const float*)d_in[2];
    const float* Wq     = (const float*)d_in[3];
    const float* Wk     = (const float*)d_in[4];
    const float* Wv     = (const float*)d_in[5];
    const float* Wp     = (const float*)d_in[6];
    const float* bp     = (const float*)d_in[7];
    const float* ln1_g  = (const float*)d_in[8];
    const float* ln1_b  = (const float*)d_in[9];
    const float* ln2_g  = (const float*)d_in[10];
    const float* ln2_b  = (const float*)d_in[11];
    const float* W1     = (const float*)d_in[12];
    const float* b1     = (const float*)d_in[13];
    const float* W2     = (const float*)d_in[14];
    const float* b2     = (const float*)d_in[15];
    const float* lnf_g  = (const float*)d_in[16];
    const float* lnf_b  = (const float*)d_in[17];
    const float* Wout   = (const float*)d_in[18];

    float *x, *qkv;
    bf16 *hh, *hl, *ohh, *ohl, *uh, *ul;
    bf16 *wqkvh, *wqkvl, *wph, *wpl, *w1h, *w1l, *w2h, *w2l, *woh, *wol;
    cudaGetSymbolAddress((void**)&x, g_x);
    cudaGetSymbolAddress((void**)&qkv, g_qkv);
    cudaGetSymbolAddress((void**)&hh, g_h_h);
    cudaGetSymbolAddress((void**)&hl, g_h_l);
    cudaGetSymbolAddress((void**)&ohh, g_o_h);
    cudaGetSymbolAddress((void**)&ohl, g_o_l);
    cudaGetSymbolAddress((void**)&uh, g_u_h);
    cudaGetSymbolAddress((void**)&ul, g_u_l);
    cudaGetSymbolAddress((void**)&wqkvh, g_Wqkv_h); cudaGetSymbolAddress((void**)&wqkvl, g_Wqkv_l);
    cudaGetSymbolAddress((void**)&wph, g_Wp_h);     cudaGetSymbolAddress((void**)&wpl, g_Wp_l);
    cudaGetSymbolAddress((void**)&w1h, g_W1_h);     cudaGetSymbolAddress((void**)&w1l, g_W1_l);
    cudaGetSymbolAddress((void**)&w2h, g_W2_h);     cudaGetSymbolAddress((void**)&w2l, g_W2_l);
    cudaGetSymbolAddress((void**)&woh, g_Wo_h);     cudaGetSymbolAddress((void**)&wol, g_Wo_l);

    cudaFuncSetAttribute(mgemm6_kernel, cudaFuncAttributeMaxDynamicSharedMemorySize, MG_SMEM);
    cudaFuncSetAttribute(fattn_kernel, cudaFuncAttributeMaxDynamicSharedMemorySize, FA_SMEM);

    tconv_all<<<130304, dim3(32, 8)>>>(Wq, Wk, Wv, Wp, W1, W2, Wout,
                                       wqkvh, wqkvl, wph, wpl, w1h, w1l,
                                       w2h, w2l, woh, wol);
    embed_kernel<<<NTOK, 256>>>(idx, tok, pos, x);

    dim3 gQKV(NTOK / 128, 3 * EMB / 128);
    dim3 gE(NTOK / 128, EMB / 128);
    dim3 gH(NTOK / 128, HID / 128);
    dim3 gV(NTOK / 128, VOCAB / 128);
    dim3 gA(SEQ / 64, 2 * NH);

    for (int l = 0; l < NL; l++) {
        size_t wo = (size_t)l * EMB * EMB;
        size_t wqo = (size_t)l * 3 * EMB * EMB;
        size_t w1o = (size_t)l * EMB * HID;

        ln_kernel<<<NTOK, 256>>>(x, ln1_g + l * EMB, ln1_b + l * EMB, hh, hl);
        mgemm6_kernel<<<gQKV, 512, MG_SMEM>>>(hh, hl, wqkvh + wqo, wqkvl + wqo,
                                              nullptr, nullptr, qkv, nullptr, nullptr,
                                              NTOK, 3 * EMB, EMB, 0);
        fattn_kernel<<<gA, 128, FA_SMEM>>>(qkv, ohh, ohl);
        mgemm6_kernel<<<gE, 512, MG_SMEM>>>(ohh, ohl, wph + wo, wpl + wo, bp + l * EMB, x,
                                            x, nullptr, nullptr, NTOK, EMB, EMB,
                                            FLAG_BIAS | FLAG_RES);
        ln_kernel<<<NTOK, 256>>>(x, ln2_g + l * EMB, ln2_b + l * EMB, hh, hl);
        mgemm6_kernel<<<gH, 512, MG_SMEM>>>(hh, hl, w1h + w1o, w1l + w1o, b1 + l * HID,
                                            nullptr, nullptr, uh, ul, NTOK, HID, EMB,
                                            FLAG_BIAS | FLAG_GELU | FLAG_OSPL);
        mgemm6_kernel<<<gE, 512, MG_SMEM>>>(uh, ul, w2h + w1o, w2l + w1o, b2 + l * EMB, x,
                                            x, nullptr, nullptr, NTOK, EMB, HID,
                                            FLAG_BIAS | FLAG_RES);
    }

    ln_kernel<<<NTOK, 256>>>(x, lnf_g, lnf_b, hh, hl);
    mgemm6_kernel<<<gV, 512, MG_SMEM>>>(hh, hl, woh, wol, nullptr, nullptr,
                                        (float*)d_out, nullptr, nullptr,
                                        NTOK, VOCAB, EMB, 0);
}